// round 4
// baseline (speedup 1.0000x reference)
#include <cuda_runtime.h>

#define NUM_NODES 100000
#define HID 64

// Scratch tables (allocation-free rule: __device__ globals).
// U[n][j] = sum_k z_user[n][k]  * W1[j][k]      + b1[j]
// B[n][j] = sum_k z_books[n][k] * W1[j][64+k]
__device__ float g_U[NUM_NODES * HID];
__device__ float g_B[NUM_NODES * HID];

// ---------------------------------------------------------------------------
// Phase 1: per-node projection. One warp handles 32 nodes (one node per lane).
// z row lives in registers; W is broadcast from shared via LDS.128 so the
// instruction mix is FMA-bound (16 FMA per LDS.128), not smem-bound.
// 100000 % 32 == 0, so no tail guards on lanes.
// ---------------------------------------------------------------------------
__global__ __launch_bounds__(256) void precompute_kernel(
    const float* __restrict__ z_user,
    const float* __restrict__ z_books,
    const float* __restrict__ W1,   // [64][128]
    const float* __restrict__ b1)   // [64]
{
    __shared__ float Wu[64 * 64];   // W1[j][k],      k in [0,64)
    __shared__ float Wb[64 * 64];   // W1[j][64+k]
    __shared__ float b1s[64];

    int tid = threadIdx.x;
    for (int i = tid; i < 64 * 64; i += blockDim.x) {
        int j = i >> 6, k = i & 63;
        Wu[i] = W1[j * 128 + k];
        Wb[i] = W1[j * 128 + 64 + k];
    }
    if (tid < 64) b1s[tid] = b1[tid];
    __syncthreads();

    const int NTILES = NUM_NODES / 32;           // 3125 per table
    int gw = (blockIdx.x * blockDim.x + tid) >> 5;
    if (gw >= 2 * NTILES) return;
    int lane = tid & 31;

    bool isU = (gw < NTILES);
    int n = (isU ? gw : gw - NTILES) * 32 + lane;

    const float* z  = isU ? z_user : z_books;
    const float* Ws = isU ? Wu : Wb;
    float*       op = (isU ? g_U : g_B) + (size_t)n * HID;

    // z row -> 64 registers (float4 loads; lanes stride 256B, rows contiguous)
    float zr[64];
    const float4* z4 = (const float4*)(z + (size_t)n * HID);
    #pragma unroll
    for (int k4 = 0; k4 < 16; k4++) {
        float4 v = z4[k4];
        zr[4 * k4 + 0] = v.x; zr[4 * k4 + 1] = v.y;
        zr[4 * k4 + 2] = v.z; zr[4 * k4 + 3] = v.w;
    }

    const float4* Ws4 = (const float4*)Ws;       // [j][k4] : j*16 + k4

    #pragma unroll 1
    for (int j = 0; j < 64; j += 4) {
        float a0 = isU ? b1s[j + 0] : 0.f;
        float a1 = isU ? b1s[j + 1] : 0.f;
        float a2 = isU ? b1s[j + 2] : 0.f;
        float a3 = isU ? b1s[j + 3] : 0.f;
        #pragma unroll
        for (int k4 = 0; k4 < 16; k4++) {
            float4 w0 = Ws4[(j + 0) * 16 + k4];  // broadcast (same addr all lanes)
            float4 w1 = Ws4[(j + 1) * 16 + k4];
            float4 w2 = Ws4[(j + 2) * 16 + k4];
            float4 w3 = Ws4[(j + 3) * 16 + k4];
            float z0 = zr[4 * k4 + 0], z1 = zr[4 * k4 + 1];
            float z2 = zr[4 * k4 + 2], z3 = zr[4 * k4 + 3];
            a0 += z0 * w0.x + z1 * w0.y + z2 * w0.z + z3 * w0.w;
            a1 += z0 * w1.x + z1 * w1.y + z2 * w1.z + z3 * w1.w;
            a2 += z0 * w2.x + z1 * w2.y + z2 * w2.z + z3 * w2.w;
            a3 += z0 * w3.x + z1 * w3.y + z2 * w3.z + z3 * w3.w;
        }
        float4 o; o.x = a0; o.y = a1; o.z = a2; o.w = a3;
        ((float4*)op)[j >> 2] = o;
    }
}

// ---------------------------------------------------------------------------
// Phase 2: per-edge decode. 16 lanes per edge (2 edges per warp), float4
// gathers of the 256B U/B rows (L2-resident), relu+dot, 16-lane shfl reduce.
// Indices are int32 (JAX default x64-disabled demotes int64 -> int32).
// ---------------------------------------------------------------------------
__global__ __launch_bounds__(256) void edge_kernel(
    const int* __restrict__ idx,         // [2][E] int32
    const float* __restrict__ W2,        // [1][64]
    const float* __restrict__ b2,        // [1]
    float* __restrict__ out,             // [E]
    int E)
{
    int lane = threadIdx.x & 31;
    int half = lane >> 4;                // 0 or 1: which edge within the warp
    int l16  = lane & 15;                // feature chunk: 4 floats per lane

    float4 w2v = ((const float4*)W2)[l16];
    float  b2v = b2[0];

    int gw = (blockIdx.x * blockDim.x + threadIdx.x) >> 5;
    int warps = (gridDim.x * blockDim.x) >> 5;

    for (int e0 = gw * 2; e0 < E; e0 += warps * 2) {
        int e = e0 + half;               // E even, e0 even -> e < E
        int r = idx[e];
        int c = idx[E + e];

        float4 u  = ((const float4*)(g_U + (size_t)r * HID))[l16];
        float4 bv = ((const float4*)(g_B + (size_t)c * HID))[l16];

        float h0 = fmaxf(u.x + bv.x, 0.f);
        float h1 = fmaxf(u.y + bv.y, 0.f);
        float h2 = fmaxf(u.z + bv.z, 0.f);
        float h3 = fmaxf(u.w + bv.w, 0.f);

        float p = h0 * w2v.x + h1 * w2v.y + h2 * w2v.z + h3 * w2v.w;
        // reduce across the 16 lanes of this half-warp
        p += __shfl_xor_sync(0xffffffff, p, 1);
        p += __shfl_xor_sync(0xffffffff, p, 2);
        p += __shfl_xor_sync(0xffffffff, p, 4);
        p += __shfl_xor_sync(0xffffffff, p, 8);

        if (l16 == 0) out[e] = p + b2v;
    }
}

// ---------------------------------------------------------------------------
extern "C" void kernel_launch(void* const* d_in, const int* in_sizes, int n_in,
                              void* d_out, int out_size)
{
    const float* z_user  = (const float*)d_in[0];
    const float* z_books = (const float*)d_in[1];
    const int*   idx     = (const int*)d_in[2];
    const float* W1      = (const float*)d_in[3];
    const float* b1      = (const float*)d_in[4];
    const float* W2      = (const float*)d_in[5];
    const float* b2      = (const float*)d_in[6];
    float*       out     = (float*)d_out;

    int E = in_sizes[2] / 2;             // edge_label_index is [2, E]

    // Phase 1: 2*3125 warp-tiles, 8 warps/block -> 782 blocks
    precompute_kernel<<<782, 256>>>(z_user, z_books, W1, b1);

    // Phase 2: grid-stride; 2048 blocks * 8 warps * 2 edges = 32768 edges/iter
    edge_kernel<<<2048, 256>>>(idx, W2, b2, out, E);
}

// round 5
// speedup vs baseline: 1.0380x; 1.0380x over previous
#include <cuda_runtime.h>

#define NUM_NODES 100000
#define HID 64

// Scratch tables (allocation-free rule: __device__ globals).
// U[n][j] = sum_k z_user[n][k]  * W1[j][k]      + b1[j]
// B[n][j] = sum_k z_books[n][k] * W1[j][64+k]
__device__ float g_U[NUM_NODES * HID];
__device__ float g_B[NUM_NODES * HID];

// ---- packed f32x2 helpers (sm_103a FFMA2 — only reachable via PTX) --------
__device__ __forceinline__ unsigned long long pack2(float x, float y) {
    unsigned long long r;
    asm("mov.b64 %0, {%1, %2};"
        : "=l"(r) : "r"(__float_as_uint(x)), "r"(__float_as_uint(y)));
    return r;
}
__device__ __forceinline__ void ffma2(unsigned long long& a,
                                      unsigned long long z,
                                      unsigned long long w) {
    asm("fma.rn.f32x2 %0, %1, %2, %0;" : "+l"(a) : "l"(z), "l"(w));
}
__device__ __forceinline__ float lo32(unsigned long long a) {
    return __uint_as_float((unsigned)a);
}
__device__ __forceinline__ float hi32(unsigned long long a) {
    return __uint_as_float((unsigned)(a >> 32));
}

// ---------------------------------------------------------------------------
// Phase 1: per-node projection, one node per thread.
// Pairing is over K: acc2_j = (sum_{even k} z_k w_jk , sum_{odd k} z_k w_jk),
// so both z-pairs and w-pairs are memory-adjacent — zero repacking.
// Per thread: 2048 FFMA2 (fma pipe) + 1024 LDS.128 broadcast (LSU pipe).
// ---------------------------------------------------------------------------
__global__ __launch_bounds__(256) void precompute_kernel(
    const float* __restrict__ z_user,
    const float* __restrict__ z_books,
    const float* __restrict__ W1,   // [64][128]
    const float* __restrict__ b1)   // [64]
{
    __shared__ float Wu[64 * 64];   // W1[j][k]      (user half)
    __shared__ float Wb[64 * 64];   // W1[j][64+k]   (book half)
    __shared__ float b1s[64];

    int tid = threadIdx.x;
    for (int i = tid; i < 64 * 64; i += 256) {
        int j = i >> 6, k = i & 63;
        Wu[i] = W1[j * 128 + k];
        Wb[i] = W1[j * 128 + 64 + k];
    }
    if (tid < 64) b1s[tid] = b1[tid];
    __syncthreads();

    int g = blockIdx.x * 256 + tid;
    if (g >= 2 * NUM_NODES) return;
    bool isU = (g < NUM_NODES);
    int n = isU ? g : g - NUM_NODES;

    const float* z  = isU ? z_user : z_books;
    const float* Ws = isU ? Wu : Wb;
    float*       op = (isU ? g_U : g_B) + (size_t)n * HID;

    // z row -> 32 packed f32x2 regs (pairs of adjacent k)
    unsigned long long zp[32];
    const float4* z4 = (const float4*)(z + (size_t)n * HID);
    #pragma unroll
    for (int i = 0; i < 16; i++) {
        float4 v = z4[i];
        zp[2 * i]     = pack2(v.x, v.y);
        zp[2 * i + 1] = pack2(v.z, v.w);
    }

    #pragma unroll 1
    for (int jb = 0; jb < 8; jb++) {          // 8 output rows per tile
        unsigned long long acc[8];
        #pragma unroll
        for (int p = 0; p < 8; p++) acc[p] = 0ull;

        #pragma unroll
        for (int k4 = 0; k4 < 16; k4++) {     // 4 k per step (2 FFMA2)
            #pragma unroll
            for (int p = 0; p < 8; p++) {
                ulonglong2 w = *(const ulonglong2*)(Ws + (jb * 8 + p) * 64 + k4 * 4);
                ffma2(acc[p], zp[2 * k4],     w.x);
                ffma2(acc[p], zp[2 * k4 + 1], w.y);
            }
        }

        float r[8];
        #pragma unroll
        for (int p = 0; p < 8; p++) {
            float a = lo32(acc[p]) + hi32(acc[p]);
            if (isU) a += b1s[jb * 8 + p];
            r[p] = a;
        }
        ((float4*)op)[jb * 2]     = make_float4(r[0], r[1], r[2], r[3]);
        ((float4*)op)[jb * 2 + 1] = make_float4(r[4], r[5], r[6], r[7]);
    }
}

// ---------------------------------------------------------------------------
// Phase 2: per-edge decode. 8 lanes per edge (4 edges per warp-pass),
// 8 edges per warp per trip -> 8 independent LDG.128 gathers in flight per
// thread (MLP ~10 incl. idx), 3-level shuffle reduce.
// ---------------------------------------------------------------------------
__global__ __launch_bounds__(256) void edge_kernel(
    const int* __restrict__ idx,         // [2][E] int32
    const float* __restrict__ W2,        // [1][64]
    const float* __restrict__ b2,        // [1]
    float* __restrict__ out,             // [E]
    int E)
{
    int lane = threadIdx.x & 31;
    int q  = lane >> 3;                  // edge slot within warp-pass (0..3)
    int l8 = lane & 7;                   // feature chunk: 8 floats per lane

    float4 w0 = ((const float4*)W2)[2 * l8];
    float4 w1 = ((const float4*)W2)[2 * l8 + 1];
    float  b2v = b2[0];

    int gw = (blockIdx.x * blockDim.x + threadIdx.x) >> 5;
    int warps = (gridDim.x * blockDim.x) >> 5;

    for (int e0 = gw * 8; e0 < E; e0 += warps * 8) {
        int eA = e0 + q;
        int eB = e0 + 4 + q;
        bool vA = (eA < E);
        bool vB = (eB < E);

        int rA = vA ? idx[eA]     : 0;
        int cA = vA ? idx[E + eA] : 0;
        int rB = vB ? idx[eB]     : 0;
        int cB = vB ? idx[E + eB] : 0;

        const float4* Ua = (const float4*)(g_U + (size_t)rA * HID);
        const float4* Ba = (const float4*)(g_B + (size_t)cA * HID);
        const float4* Ub = (const float4*)(g_U + (size_t)rB * HID);
        const float4* Bb = (const float4*)(g_B + (size_t)cB * HID);

        // 8 independent gathers (each half-row chunk of 32B)
        float4 uA0 = Ua[2 * l8], uA1 = Ua[2 * l8 + 1];
        float4 bA0 = Ba[2 * l8], bA1 = Ba[2 * l8 + 1];
        float4 uB0 = Ub[2 * l8], uB1 = Ub[2 * l8 + 1];
        float4 bB0 = Bb[2 * l8], bB1 = Bb[2 * l8 + 1];

        float pA, pB;
        {
            float h0 = fmaxf(uA0.x + bA0.x, 0.f), h1 = fmaxf(uA0.y + bA0.y, 0.f);
            float h2 = fmaxf(uA0.z + bA0.z, 0.f), h3 = fmaxf(uA0.w + bA0.w, 0.f);
            float h4 = fmaxf(uA1.x + bA1.x, 0.f), h5 = fmaxf(uA1.y + bA1.y, 0.f);
            float h6 = fmaxf(uA1.z + bA1.z, 0.f), h7 = fmaxf(uA1.w + bA1.w, 0.f);
            pA = h0 * w0.x + h1 * w0.y + h2 * w0.z + h3 * w0.w
               + h4 * w1.x + h5 * w1.y + h6 * w1.z + h7 * w1.w;
        }
        {
            float h0 = fmaxf(uB0.x + bB0.x, 0.f), h1 = fmaxf(uB0.y + bB0.y, 0.f);
            float h2 = fmaxf(uB0.z + bB0.z, 0.f), h3 = fmaxf(uB0.w + bB0.w, 0.f);
            float h4 = fmaxf(uB1.x + bB1.x, 0.f), h5 = fmaxf(uB1.y + bB1.y, 0.f);
            float h6 = fmaxf(uB1.z + bB1.z, 0.f), h7 = fmaxf(uB1.w + bB1.w, 0.f);
            pB = h0 * w0.x + h1 * w0.y + h2 * w0.z + h3 * w0.w
               + h4 * w1.x + h5 * w1.y + h6 * w1.z + h7 * w1.w;
        }

        // interleaved 8-lane reductions (independent chains hide SHFL latency)
        pA += __shfl_xor_sync(0xffffffffu, pA, 1);
        pB += __shfl_xor_sync(0xffffffffu, pB, 1);
        pA += __shfl_xor_sync(0xffffffffu, pA, 2);
        pB += __shfl_xor_sync(0xffffffffu, pB, 2);
        pA += __shfl_xor_sync(0xffffffffu, pA, 4);
        pB += __shfl_xor_sync(0xffffffffu, pB, 4);

        if (l8 == 0) {
            if (vA) out[eA] = pA + b2v;
            if (vB) out[eB] = pB + b2v;
        }
    }
}

// ---------------------------------------------------------------------------
extern "C" void kernel_launch(void* const* d_in, const int* in_sizes, int n_in,
                              void* d_out, int out_size)
{
    const float* z_user  = (const float*)d_in[0];
    const float* z_books = (const float*)d_in[1];
    const int*   idx     = (const int*)d_in[2];
    const float* W1      = (const float*)d_in[3];
    const float* b1      = (const float*)d_in[4];
    const float* W2      = (const float*)d_in[5];
    const float* b2      = (const float*)d_in[6];
    float*       out     = (float*)d_out;

    int E = in_sizes[2] / 2;             // edge_label_index is [2, E]

    // Phase 1: one node per thread, 200000 threads
    precompute_kernel<<<(2 * NUM_NODES + 255) / 256, 256>>>(z_user, z_books, W1, b1);

    // Phase 2: grid-stride; 16384 warps * 8 edges per trip
    edge_kernel<<<2048, 256>>>(idx, W2, b2, out, E);
}

// round 7
// speedup vs baseline: 1.5137x; 1.4582x over previous
#include <cuda_runtime.h>
#include <cuda_bf16.h>
#include <cstdint>

#define NUM_NODES 100000
#define HID 64
#define WTILES_PER_HALF (NUM_NODES / 16)      // 6250 warp-tiles per table
#define WTILES_TOTAL (2 * WTILES_PER_HALF)    // 12500

// Scratch tables (allocation-free rule: __device__ globals).
__device__ float g_U[NUM_NODES * HID];
__device__ float g_B[NUM_NODES * HID];

// ---- bf16 helpers ----------------------------------------------------------
__device__ __forceinline__ uint32_t pack_bf2(__nv_bfloat16 a, __nv_bfloat16 b) {
    __nv_bfloat162 t = __halves2bfloat162(a, b);   // a -> low, b -> high
    return *reinterpret_cast<uint32_t*>(&t);
}
// split a float2 into packed bf16 hi-pair and lo-pair (hi+lo ~ full fp32)
__device__ __forceinline__ void split2(float2 v, uint32_t& hi, uint32_t& lo) {
    __nv_bfloat16 h0 = __float2bfloat16(v.x);
    __nv_bfloat16 h1 = __float2bfloat16(v.y);
    hi = pack_bf2(h0, h1);
    lo = pack_bf2(__float2bfloat16(v.x - __bfloat162float(h0)),
                  __float2bfloat16(v.y - __bfloat162float(h1)));
}
__device__ __forceinline__ void mma_bf16(float* c, uint32_t a0, uint32_t a1,
                                         uint32_t a2, uint32_t a3,
                                         uint32_t b0, uint32_t b1) {
    asm volatile(
        "mma.sync.aligned.m16n8k16.row.col.f32.bf16.bf16.f32 "
        "{%0,%1,%2,%3}, {%4,%5,%6,%7}, {%8,%9}, {%0,%1,%2,%3};"
        : "+f"(c[0]), "+f"(c[1]), "+f"(c[2]), "+f"(c[3])
        : "r"(a0), "r"(a1), "r"(a2), "r"(a3), "r"(b0), "r"(b1));
}

// W smem: packed-bf16 u32, [half(u/b)][hi/lo][j=0..63][k2=0..31], row padded
// to 36 u32 (stride % 32 == 4 -> bank = 4g+tc, all 32 lanes distinct).
#define WROW 36
__device__ __forceinline__ int widx(int half, int hl, int j, int k2) {
    return ((half * 2 + hl) * 64 + j) * WROW + k2;
}

// ---------------------------------------------------------------------------
// Phase 1: split-bf16 HMMA GEMM (mma.sync m16n8k16; tcgen05 is an 'a'-target
// feature the harness's compute_103 PTX pass rejects).
// D = z_hi*W_hi + z_hi*W_lo + z_lo*W_hi, fp32 accumulate (err ~2^-16).
// One warp = 16 nodes x 64 outputs. Warp-tiles [0,6250) -> U, rest -> B.
// ---------------------------------------------------------------------------
__global__ __launch_bounds__(256) void precompute_mma(
    const float* __restrict__ z_user,
    const float* __restrict__ z_books,
    const float* __restrict__ W1,    // [64][128]
    const float* __restrict__ b1)    // [64]
{
    __shared__ uint32_t Wq[2 * 2 * 64 * WROW];
    __shared__ float b1s[64];

    int tid = threadIdx.x;
    // convert both halves of W1 into packed bf16 hi/lo (2*64*32 u32-pairs)
    for (int i = tid; i < 2 * 64 * 32; i += 256) {
        int half = i >> 11;            // 0=user cols, 1=book cols
        int j    = (i >> 5) & 63;
        int k2   = i & 31;
        float2 w = *(const float2*)(W1 + j * 128 + half * 64 + k2 * 2);
        uint32_t hi, lo;
        split2(w, hi, lo);
        Wq[widx(half, 0, j, k2)] = hi;
        Wq[widx(half, 1, j, k2)] = lo;
    }
    if (tid < 64) b1s[tid] = b1[tid];
    __syncthreads();

    int wid = tid >> 5, lane = tid & 31;
    int wt = blockIdx.x * 8 + wid;
    if (wt >= WTILES_TOTAL) return;

    bool isU = (wt < WTILES_PER_HALF);
    int tile = isU ? wt : wt - WTILES_PER_HALF;
    int nb = tile * 16;
    const float* z = isU ? z_user : z_books;
    int half = isU ? 0 : 1;

    int g = lane >> 2, tc = lane & 3;

    const float2* zr0 = (const float2*)(z + (size_t)(nb + g) * HID);
    const float2* zr1 = (const float2*)(z + (size_t)(nb + g + 8) * HID);

    float acc[8][4];
    #pragma unroll
    for (int jt = 0; jt < 8; jt++)
        #pragma unroll
        for (int c = 0; c < 4; c++) acc[jt][c] = 0.f;

    #pragma unroll
    for (int ks = 0; ks < 4; ks++) {
        // A fragments for this k-step (rows g, g+8; k = ks*16 + {tc*2, tc*2+8})
        float2 p00 = zr0[ks * 8 + tc],     p02 = zr0[ks * 8 + tc + 4];
        float2 p10 = zr1[ks * 8 + tc],     p12 = zr1[ks * 8 + tc + 4];
        uint32_t a0h, a0l, a1h, a1l, a2h, a2l, a3h, a3l;
        split2(p00, a0h, a0l);
        split2(p10, a1h, a1l);
        split2(p02, a2h, a2l);
        split2(p12, a3h, a3l);

        // B fragments: col j = jt*8 + g, k2 = ks*8 + tc (b0) / +4 (b1)
        uint32_t bh0[8], bh1[8], bl0[8], bl1[8];
        #pragma unroll
        for (int jt = 0; jt < 8; jt++) {
            int j = jt * 8 + g;
            bh0[jt] = Wq[widx(half, 0, j, ks * 8 + tc)];
            bh1[jt] = Wq[widx(half, 0, j, ks * 8 + tc + 4)];
            bl0[jt] = Wq[widx(half, 1, j, ks * 8 + tc)];
            bl1[jt] = Wq[widx(half, 1, j, ks * 8 + tc + 4)];
        }

        #pragma unroll
        for (int jt = 0; jt < 8; jt++)   // pass 1: z_hi * W_hi
            mma_bf16(acc[jt], a0h, a1h, a2h, a3h, bh0[jt], bh1[jt]);
        #pragma unroll
        for (int jt = 0; jt < 8; jt++)   // pass 2: z_hi * W_lo
            mma_bf16(acc[jt], a0h, a1h, a2h, a3h, bl0[jt], bl1[jt]);
        #pragma unroll
        for (int jt = 0; jt < 8; jt++)   // pass 3: z_lo * W_hi
            mma_bf16(acc[jt], a0l, a1l, a2l, a3l, bh0[jt], bh1[jt]);
    }

    // Epilogue: c0,c1 -> (row g, cols n0,n0+1); c2,c3 -> (row g+8).
    float* table = isU ? g_U : g_B;
    float2* o0 = (float2*)(table + (size_t)(nb + g) * HID);
    float2* o1 = (float2*)(table + (size_t)(nb + g + 8) * HID);
    #pragma unroll
    for (int jt = 0; jt < 8; jt++) {
        int n2 = jt * 4 + tc;            // float2 column index (col = 2*n2)
        float bx = 0.f, by = 0.f;
        if (isU) { bx = b1s[2 * n2]; by = b1s[2 * n2 + 1]; }
        o0[n2] = make_float2(acc[jt][0] + bx, acc[jt][1] + by);
        o1[n2] = make_float2(acc[jt][2] + bx, acc[jt][3] + by);
    }
}

// ---------------------------------------------------------------------------
// Phase 2: per-edge decode (at L2 roofline ~12 TB/s — unchanged from R4/R5).
// ---------------------------------------------------------------------------
__global__ __launch_bounds__(256) void edge_kernel(
    const int* __restrict__ idx,         // [2][E] int32
    const float* __restrict__ W2,        // [1][64]
    const float* __restrict__ b2,        // [1]
    float* __restrict__ out,             // [E]
    int E)
{
    int lane = threadIdx.x & 31;
    int q  = lane >> 3;                  // edge slot within warp-pass (0..3)
    int l8 = lane & 7;                   // feature chunk: 8 floats per lane

    float4 w0 = ((const float4*)W2)[2 * l8];
    float4 w1 = ((const float4*)W2)[2 * l8 + 1];
    float  b2v = b2[0];

    int gw = (blockIdx.x * blockDim.x + threadIdx.x) >> 5;
    int warps = (gridDim.x * blockDim.x) >> 5;

    for (int e0 = gw * 8; e0 < E; e0 += warps * 8) {
        int eA = e0 + q;
        int eB = e0 + 4 + q;
        bool vA = (eA < E);
        bool vB = (eB < E);

        int rA = vA ? idx[eA]     : 0;
        int cA = vA ? idx[E + eA] : 0;
        int rB = vB ? idx[eB]     : 0;
        int cB = vB ? idx[E + eB] : 0;

        const float4* Ua = (const float4*)(g_U + (size_t)rA * HID);
        const float4* Ba = (const float4*)(g_B + (size_t)cA * HID);
        const float4* Ub = (const float4*)(g_U + (size_t)rB * HID);
        const float4* Bb = (const float4*)(g_B + (size_t)cB * HID);

        float4 uA0 = Ua[2 * l8], uA1 = Ua[2 * l8 + 1];
        float4 bA0 = Ba[2 * l8], bA1 = Ba[2 * l8 + 1];
        float4 uB0 = Ub[2 * l8], uB1 = Ub[2 * l8 + 1];
        float4 bB0 = Bb[2 * l8], bB1 = Bb[2 * l8 + 1];

        float pA, pB;
        {
            float h0 = fmaxf(uA0.x + bA0.x, 0.f), h1 = fmaxf(uA0.y + bA0.y, 0.f);
            float h2 = fmaxf(uA0.z + bA0.z, 0.f), h3 = fmaxf(uA0.w + bA0.w, 0.f);
            float h4 = fmaxf(uA1.x + bA1.x, 0.f), h5 = fmaxf(uA1.y + bA1.y, 0.f);
            float h6 = fmaxf(uA1.z + bA1.z, 0.f), h7 = fmaxf(uA1.w + bA1.w, 0.f);
            pA = h0 * w0.x + h1 * w0.y + h2 * w0.z + h3 * w0.w
               + h4 * w1.x + h5 * w1.y + h6 * w1.z + h7 * w1.w;
        }
        {
            float h0 = fmaxf(uB0.x + bB0.x, 0.f), h1 = fmaxf(uB0.y + bB0.y, 0.f);
            float h2 = fmaxf(uB0.z + bB0.z, 0.f), h3 = fmaxf(uB0.w + bB0.w, 0.f);
            float h4 = fmaxf(uB1.x + bB1.x, 0.f), h5 = fmaxf(uB1.y + bB1.y, 0.f);
            float h6 = fmaxf(uB1.z + bB1.z, 0.f), h7 = fmaxf(uB1.w + bB1.w, 0.f);
            pB = h0 * w0.x + h1 * w0.y + h2 * w0.z + h3 * w0.w
               + h4 * w1.x + h5 * w1.y + h6 * w1.z + h7 * w1.w;
        }

        pA += __shfl_xor_sync(0xffffffffu, pA, 1);
        pB += __shfl_xor_sync(0xffffffffu, pB, 1);
        pA += __shfl_xor_sync(0xffffffffu, pA, 2);
        pB += __shfl_xor_sync(0xffffffffu, pB, 2);
        pA += __shfl_xor_sync(0xffffffffu, pA, 4);
        pB += __shfl_xor_sync(0xffffffffu, pB, 4);

        if (l8 == 0) {
            if (vA) out[eA] = pA + b2v;
            if (vB) out[eB] = pB + b2v;
        }
    }
}

// ---------------------------------------------------------------------------
extern "C" void kernel_launch(void* const* d_in, const int* in_sizes, int n_in,
                              void* d_out, int out_size)
{
    const float* z_user  = (const float*)d_in[0];
    const float* z_books = (const float*)d_in[1];
    const int*   idx     = (const int*)d_in[2];
    const float* W1      = (const float*)d_in[3];
    const float* b1      = (const float*)d_in[4];
    const float* W2      = (const float*)d_in[5];
    const float* b2      = (const float*)d_in[6];
    float*       out     = (float*)d_out;

    int E = in_sizes[2] / 2;             // edge_label_index is [2, E]

    // Phase 1: 12500 warp-tiles, 8 warps/block -> 1563 blocks
    precompute_mma<<<(WTILES_TOTAL + 7) / 8, 256>>>(z_user, z_books, W1, b1);

    // Phase 2: grid-stride; 16384 warps * 8 edges per trip
    edge_kernel<<<2048, 256>>>(idx, W2, b2, out, E);
}

// round 8
// speedup vs baseline: 1.9975x; 1.3197x over previous
#include <cuda_runtime.h>
#include <cuda_bf16.h>
#include <cuda_fp16.h>
#include <cstdint>

#define NUM_NODES 100000
#define HID 64
#define WTILES_PER_HALF (NUM_NODES / 16)      // 6250 warp-tiles per table
#define WTILES_TOTAL (2 * WTILES_PER_HALF)    // 12500

// Scratch tables in fp16 (allocation-free rule: __device__ globals).
// Row = 64 half = 128 B. Halves the L2-bound edge-phase payload vs fp32.
__device__ __half g_U[NUM_NODES * HID];
__device__ __half g_B[NUM_NODES * HID];

// ---- bf16 helpers (precompute GEMM in split-bf16, fp32 accumulate) --------
__device__ __forceinline__ uint32_t pack_bf2(__nv_bfloat16 a, __nv_bfloat16 b) {
    __nv_bfloat162 t = __halves2bfloat162(a, b);   // a -> low, b -> high
    return *reinterpret_cast<uint32_t*>(&t);
}
__device__ __forceinline__ void split2(float2 v, uint32_t& hi, uint32_t& lo) {
    __nv_bfloat16 h0 = __float2bfloat16(v.x);
    __nv_bfloat16 h1 = __float2bfloat16(v.y);
    hi = pack_bf2(h0, h1);
    lo = pack_bf2(__float2bfloat16(v.x - __bfloat162float(h0)),
                  __float2bfloat16(v.y - __bfloat162float(h1)));
}
__device__ __forceinline__ void mma_bf16(float* c, uint32_t a0, uint32_t a1,
                                         uint32_t a2, uint32_t a3,
                                         uint32_t b0, uint32_t b1) {
    asm volatile(
        "mma.sync.aligned.m16n8k16.row.col.f32.bf16.bf16.f32 "
        "{%0,%1,%2,%3}, {%4,%5,%6,%7}, {%8,%9}, {%0,%1,%2,%3};"
        : "+f"(c[0]), "+f"(c[1]), "+f"(c[2]), "+f"(c[3])
        : "r"(a0), "r"(a1), "r"(a2), "r"(a3), "r"(b0), "r"(b1));
}

// W smem: packed-bf16 u32, [half(u/b)][hi/lo][j=0..63][k2=0..31], row padded
// to 36 u32 (stride % 32 == 4 -> bank = 4g+tc, all 32 lanes distinct).
#define WROW 36
__device__ __forceinline__ int widx(int half, int hl, int j, int k2) {
    return ((half * 2 + hl) * 64 + j) * WROW + k2;
}

// ---------------------------------------------------------------------------
// Phase 1: split-bf16 HMMA GEMM (mma.sync m16n8k16 — compute_103-legal).
// D = z_hi*W_hi + z_hi*W_lo + z_lo*W_hi, fp32 accumulate, fp16 store.
// One warp = 16 nodes x 64 outputs. Warp-tiles [0,6250) -> U, rest -> B.
// ---------------------------------------------------------------------------
__global__ __launch_bounds__(256) void precompute_mma(
    const float* __restrict__ z_user,
    const float* __restrict__ z_books,
    const float* __restrict__ W1,    // [64][128]
    const float* __restrict__ b1)    // [64]
{
    __shared__ uint32_t Wq[2 * 2 * 64 * WROW];
    __shared__ float b1s[64];

    int tid = threadIdx.x;
    for (int i = tid; i < 2 * 64 * 32; i += 256) {
        int half = i >> 11;            // 0=user cols, 1=book cols
        int j    = (i >> 5) & 63;
        int k2   = i & 31;
        float2 w = *(const float2*)(W1 + j * 128 + half * 64 + k2 * 2);
        uint32_t hi, lo;
        split2(w, hi, lo);
        Wq[widx(half, 0, j, k2)] = hi;
        Wq[widx(half, 1, j, k2)] = lo;
    }
    if (tid < 64) b1s[tid] = b1[tid];
    __syncthreads();

    int wid = tid >> 5, lane = tid & 31;
    int wt = blockIdx.x * 8 + wid;
    if (wt >= WTILES_TOTAL) return;

    bool isU = (wt < WTILES_PER_HALF);
    int tile = isU ? wt : wt - WTILES_PER_HALF;
    int nb = tile * 16;
    const float* z = isU ? z_user : z_books;
    int half = isU ? 0 : 1;

    int g = lane >> 2, tc = lane & 3;

    const float2* zr0 = (const float2*)(z + (size_t)(nb + g) * HID);
    const float2* zr1 = (const float2*)(z + (size_t)(nb + g + 8) * HID);

    float acc[8][4];
    #pragma unroll
    for (int jt = 0; jt < 8; jt++)
        #pragma unroll
        for (int c = 0; c < 4; c++) acc[jt][c] = 0.f;

    #pragma unroll
    for (int ks = 0; ks < 4; ks++) {
        float2 p00 = zr0[ks * 8 + tc],     p02 = zr0[ks * 8 + tc + 4];
        float2 p10 = zr1[ks * 8 + tc],     p12 = zr1[ks * 8 + tc + 4];
        uint32_t a0h, a0l, a1h, a1l, a2h, a2l, a3h, a3l;
        split2(p00, a0h, a0l);
        split2(p10, a1h, a1l);
        split2(p02, a2h, a2l);
        split2(p12, a3h, a3l);

        uint32_t bh0[8], bh1[8], bl0[8], bl1[8];
        #pragma unroll
        for (int jt = 0; jt < 8; jt++) {
            int j = jt * 8 + g;
            bh0[jt] = Wq[widx(half, 0, j, ks * 8 + tc)];
            bh1[jt] = Wq[widx(half, 0, j, ks * 8 + tc + 4)];
            bl0[jt] = Wq[widx(half, 1, j, ks * 8 + tc)];
            bl1[jt] = Wq[widx(half, 1, j, ks * 8 + tc + 4)];
        }

        #pragma unroll
        for (int jt = 0; jt < 8; jt++)   // pass 1: z_hi * W_hi
            mma_bf16(acc[jt], a0h, a1h, a2h, a3h, bh0[jt], bh1[jt]);
        #pragma unroll
        for (int jt = 0; jt < 8; jt++)   // pass 2: z_hi * W_lo
            mma_bf16(acc[jt], a0h, a1h, a2h, a3h, bl0[jt], bl1[jt]);
        #pragma unroll
        for (int jt = 0; jt < 8; jt++)   // pass 3: z_lo * W_hi
            mma_bf16(acc[jt], a0l, a1l, a2l, a3l, bh0[jt], bh1[jt]);
    }

    // Epilogue: (c0,c1) -> row g cols (2n2, 2n2+1); (c2,c3) -> row g+8.
    __half* table = isU ? g_U : g_B;
    __half2* o0 = (__half2*)(table + (size_t)(nb + g) * HID);
    __half2* o1 = (__half2*)(table + (size_t)(nb + g + 8) * HID);
    #pragma unroll
    for (int jt = 0; jt < 8; jt++) {
        int n2 = jt * 4 + tc;            // half2 column index (col = 2*n2)
        float bx = 0.f, by = 0.f;
        if (isU) { bx = b1s[2 * n2]; by = b1s[2 * n2 + 1]; }
        o0[n2] = __floats2half2_rn(acc[jt][0] + bx, acc[jt][1] + by);
        o1[n2] = __floats2half2_rn(acc[jt][2] + bx, acc[jt][3] + by);
    }
}

// ---------------------------------------------------------------------------
// Phase 2: per-edge decode on fp16 tables. 8 lanes/edge, one LDG.128 per
// row-gather per edge (16B/lane = 8 halves), 8 edges in flight per warp.
// u+b and relu in half2 (HADD2/HMAX2), dot in fp32 for accuracy.
// ---------------------------------------------------------------------------
__global__ __launch_bounds__(256) void edge_kernel(
    const int* __restrict__ idx,         // [2][E] int32
    const float* __restrict__ W2,        // [1][64]
    const float* __restrict__ b2,        // [1]
    float* __restrict__ out,             // [E]
    int E)
{
    int lane = threadIdx.x & 31;
    int q  = lane >> 3;                  // edge slot within warp-pass (0..3)
    int l8 = lane & 7;                   // feature chunk: 8 halves per lane

    float4 w0 = ((const float4*)W2)[2 * l8];
    float4 w1 = ((const float4*)W2)[2 * l8 + 1];
    float  b2v = b2[0];

    int gw = (blockIdx.x * blockDim.x + threadIdx.x) >> 5;
    int warps = (gridDim.x * blockDim.x) >> 5;

    const __half2 zero2 = __float2half2_rn(0.f);

    for (int e0 = gw * 8; e0 < E; e0 += warps * 8) {
        int eA = e0 + q;
        int eB = e0 + 4 + q;
        bool vA = (eA < E);
        bool vB = (eB < E);

        int rA = vA ? idx[eA]     : 0;
        int cA = vA ? idx[E + eA] : 0;
        int rB = vB ? idx[eB]     : 0;
        int cB = vB ? idx[E + eB] : 0;

        // 4 independent 16B gathers per thread (8 per edge-pair slot)
        uint4 uA = *(const uint4*)(g_U + (size_t)rA * HID + l8 * 8);
        uint4 bA = *(const uint4*)(g_B + (size_t)cA * HID + l8 * 8);
        uint4 uB = *(const uint4*)(g_U + (size_t)rB * HID + l8 * 8);
        uint4 bB = *(const uint4*)(g_B + (size_t)cB * HID + l8 * 8);

        float pA, pB;
        {
            const __half2* u = (const __half2*)&uA;
            const __half2* b = (const __half2*)&bA;
            __half2 h0 = __hmax2(__hadd2(u[0], b[0]), zero2);
            __half2 h1 = __hmax2(__hadd2(u[1], b[1]), zero2);
            __half2 h2 = __hmax2(__hadd2(u[2], b[2]), zero2);
            __half2 h3 = __hmax2(__hadd2(u[3], b[3]), zero2);
            float2 f0 = __half22float2(h0), f1 = __half22float2(h1);
            float2 f2 = __half22float2(h2), f3 = __half22float2(h3);
            pA = f0.x * w0.x + f0.y * w0.y + f1.x * w0.z + f1.y * w0.w
               + f2.x * w1.x + f2.y * w1.y + f3.x * w1.z + f3.y * w1.w;
        }
        {
            const __half2* u = (const __half2*)&uB;
            const __half2* b = (const __half2*)&bB;
            __half2 h0 = __hmax2(__hadd2(u[0], b[0]), zero2);
            __half2 h1 = __hmax2(__hadd2(u[1], b[1]), zero2);
            __half2 h2 = __hmax2(__hadd2(u[2], b[2]), zero2);
            __half2 h3 = __hmax2(__hadd2(u[3], b[3]), zero2);
            float2 f0 = __half22float2(h0), f1 = __half22float2(h1);
            float2 f2 = __half22float2(h2), f3 = __half22float2(h3);
            pB = f0.x * w0.x + f0.y * w0.y + f1.x * w0.z + f1.y * w0.w
               + f2.x * w1.x + f2.y * w1.y + f3.x * w1.z + f3.y * w1.w;
        }

        pA += __shfl_xor_sync(0xffffffffu, pA, 1);
        pB += __shfl_xor_sync(0xffffffffu, pB, 1);
        pA += __shfl_xor_sync(0xffffffffu, pA, 2);
        pB += __shfl_xor_sync(0xffffffffu, pB, 2);
        pA += __shfl_xor_sync(0xffffffffu, pA, 4);
        pB += __shfl_xor_sync(0xffffffffu, pB, 4);

        if (l8 == 0) {
            if (vA) out[eA] = pA + b2v;
            if (vB) out[eB] = pB + b2v;
        }
    }
}

// ---------------------------------------------------------------------------
extern "C" void kernel_launch(void* const* d_in, const int* in_sizes, int n_in,
                              void* d_out, int out_size)
{
    const float* z_user  = (const float*)d_in[0];
    const float* z_books = (const float*)d_in[1];
    const int*   idx     = (const int*)d_in[2];
    const float* W1      = (const float*)d_in[3];
    const float* b1      = (const float*)d_in[4];
    const float* W2      = (const float*)d_in[5];
    const float* b2      = (const float*)d_in[6];
    float*       out     = (float*)d_out;

    int E = in_sizes[2] / 2;             // edge_label_index is [2, E]

    // Phase 1: 12500 warp-tiles, 8 warps/block -> 1563 blocks
    precompute_mma<<<(WTILES_TOTAL + 7) / 8, 256>>>(z_user, z_books, W1, b1);

    // Phase 2: grid-stride; 16384 warps * 8 edges per trip
    edge_kernel<<<2048, 256>>>(idx, W2, b2, out, E);
}

// round 9
// speedup vs baseline: 2.1851x; 1.0939x over previous
#include <cuda_runtime.h>
#include <cuda_bf16.h>
#include <cuda_fp16.h>
#include <cstdint>

#define NUM_NODES 100000
#define HID 64
#define WTILES_PER_HALF (NUM_NODES / 16)      // 6250 warp-tiles per table
#define WTILES_TOTAL (2 * WTILES_PER_HALF)    // 12500

// Scratch tables in fp16 (allocation-free rule: __device__ globals).
// Row = 64 half = 128 B.
__device__ __half g_U[NUM_NODES * HID];
__device__ __half g_B[NUM_NODES * HID];

// ---- packed bf16 split (hi + lo ≈ fp32), 6 ops via cvt.rn.bf16x2 ----------
__device__ __forceinline__ void split2(float2 v, uint32_t& hi, uint32_t& lo) {
    // hi = {high: bf16(v.y), low: bf16(v.x)}
    asm("cvt.rn.bf16x2.f32 %0, %1, %2;" : "=r"(hi) : "f"(v.y), "f"(v.x));
    float hx = __uint_as_float(hi << 16);          // reconstruct bf16(v.x)
    float hy = __uint_as_float(hi & 0xffff0000u);  // reconstruct bf16(v.y)
    float rx = v.x - hx, ry = v.y - hy;
    asm("cvt.rn.bf16x2.f32 %0, %1, %2;" : "=r"(lo) : "f"(ry), "f"(rx));
}
__device__ __forceinline__ void mma_bf16(float* c, uint32_t a0, uint32_t a1,
                                         uint32_t a2, uint32_t a3,
                                         uint32_t b0, uint32_t b1) {
    asm volatile(
        "mma.sync.aligned.m16n8k16.row.col.f32.bf16.bf16.f32 "
        "{%0,%1,%2,%3}, {%4,%5,%6,%7}, {%8,%9}, {%0,%1,%2,%3};"
        : "+f"(c[0]), "+f"(c[1]), "+f"(c[2]), "+f"(c[3])
        : "r"(a0), "r"(a1), "r"(a2), "r"(a3), "r"(b0), "r"(b1));
}

// W smem: packed-bf16 u32, [half(u/b)][hi/lo][j=0..63][k2=0..31], row padded
// to 36 u32 (stride % 32 == 4 -> bank = 4g+tc, all 32 lanes distinct).
#define WROW 36
__device__ __forceinline__ int widx(int half, int hl, int j, int k2) {
    return ((half * 2 + hl) * 64 + j) * WROW + k2;
}

// ---------------------------------------------------------------------------
// Phase 1: split-bf16 HMMA GEMM (mma.sync m16n8k16 — compute_103-legal).
// D = z_hi*W_hi + z_hi*W_lo + z_lo*W_hi, fp32 accumulate, fp16 store.
// One warp = 16 nodes x 64 outputs. Warp-tiles [0,6250) -> U, rest -> B.
// ---------------------------------------------------------------------------
__global__ __launch_bounds__(256) void precompute_mma(
    const float* __restrict__ z_user,
    const float* __restrict__ z_books,
    const float* __restrict__ W1,    // [64][128]
    const float* __restrict__ b1)    // [64]
{
    __shared__ uint32_t Wq[2 * 2 * 64 * WROW];
    __shared__ float b1s[64];

    int tid = threadIdx.x;
    for (int i = tid; i < 2 * 64 * 32; i += 256) {
        int half = i >> 11;            // 0=user cols, 1=book cols
        int j    = (i >> 5) & 63;
        int k2   = i & 31;
        float2 w = *(const float2*)(W1 + j * 128 + half * 64 + k2 * 2);
        uint32_t hi, lo;
        split2(w, hi, lo);
        Wq[widx(half, 0, j, k2)] = hi;
        Wq[widx(half, 1, j, k2)] = lo;
    }
    if (tid < 64) b1s[tid] = b1[tid];
    __syncthreads();

    int wid = tid >> 5, lane = tid & 31;
    int wt = blockIdx.x * 8 + wid;
    if (wt >= WTILES_TOTAL) return;

    bool isU = (wt < WTILES_PER_HALF);
    int tile = isU ? wt : wt - WTILES_PER_HALF;
    int nb = tile * 16;
    const float* z = isU ? z_user : z_books;
    int half = isU ? 0 : 1;

    int g = lane >> 2, tc = lane & 3;

    const float2* zr0 = (const float2*)(z + (size_t)(nb + g) * HID);
    const float2* zr1 = (const float2*)(z + (size_t)(nb + g + 8) * HID);

    float acc[8][4];
    #pragma unroll
    for (int jt = 0; jt < 8; jt++)
        #pragma unroll
        for (int c = 0; c < 4; c++) acc[jt][c] = 0.f;

    #pragma unroll
    for (int ks = 0; ks < 4; ks++) {
        float2 p00 = zr0[ks * 8 + tc],     p02 = zr0[ks * 8 + tc + 4];
        float2 p10 = zr1[ks * 8 + tc],     p12 = zr1[ks * 8 + tc + 4];
        uint32_t a0h, a0l, a1h, a1l, a2h, a2l, a3h, a3l;
        split2(p00, a0h, a0l);
        split2(p10, a1h, a1l);
        split2(p02, a2h, a2l);
        split2(p12, a3h, a3l);

        uint32_t bh0[8], bh1[8], bl0[8], bl1[8];
        #pragma unroll
        for (int jt = 0; jt < 8; jt++) {
            int j = jt * 8 + g;
            bh0[jt] = Wq[widx(half, 0, j, ks * 8 + tc)];
            bh1[jt] = Wq[widx(half, 0, j, ks * 8 + tc + 4)];
            bl0[jt] = Wq[widx(half, 1, j, ks * 8 + tc)];
            bl1[jt] = Wq[widx(half, 1, j, ks * 8 + tc + 4)];
        }

        #pragma unroll
        for (int jt = 0; jt < 8; jt++)   // pass 1: z_hi * W_hi
            mma_bf16(acc[jt], a0h, a1h, a2h, a3h, bh0[jt], bh1[jt]);
        #pragma unroll
        for (int jt = 0; jt < 8; jt++)   // pass 2: z_hi * W_lo
            mma_bf16(acc[jt], a0h, a1h, a2h, a3h, bl0[jt], bl1[jt]);
        #pragma unroll
        for (int jt = 0; jt < 8; jt++)   // pass 3: z_lo * W_hi
            mma_bf16(acc[jt], a0l, a1l, a2l, a3l, bh0[jt], bh1[jt]);
    }

    // Epilogue: (c0,c1) -> row g cols (2n2, 2n2+1); (c2,c3) -> row g+8.
    __half* table = isU ? g_U : g_B;
    __half2* o0 = (__half2*)(table + (size_t)(nb + g) * HID);
    __half2* o1 = (__half2*)(table + (size_t)(nb + g + 8) * HID);
    #pragma unroll
    for (int jt = 0; jt < 8; jt++) {
        int n2 = jt * 4 + tc;            // half2 column index (col = 2*n2)
        float bx = 0.f, by = 0.f;
        if (isU) { bx = b1s[2 * n2]; by = b1s[2 * n2 + 1]; }
        o0[n2] = __floats2half2_rn(acc[jt][0] + bx, acc[jt][1] + by);
        o1[n2] = __floats2half2_rn(acc[jt][2] + bx, acc[jt][3] + by);
    }
}

// ---------------------------------------------------------------------------
// Phase 2: per-edge decode on fp16 tables. 8 lanes/edge, 8 edges in flight
// per warp (4 independent LDG.128 per thread). relu+add AND dot in half2
// (HADD2/HMAX2/HFMA2); only the per-lane partial is widened to fp32 before
// the cross-lane shuffle reduce.
// ---------------------------------------------------------------------------
__global__ __launch_bounds__(256) void edge_kernel(
    const int* __restrict__ idx,         // [2][E] int32
    const float* __restrict__ W2,        // [1][64]
    const float* __restrict__ b2,        // [1]
    float* __restrict__ out,             // [E]
    int E)
{
    int lane = threadIdx.x & 31;
    int q  = lane >> 3;                  // edge slot within warp-pass (0..3)
    int l8 = lane & 7;                   // feature chunk: 8 halves per lane

    float4 w0 = ((const float4*)W2)[2 * l8];
    float4 w1 = ((const float4*)W2)[2 * l8 + 1];
    __half2 wh0 = __floats2half2_rn(w0.x, w0.y);
    __half2 wh1 = __floats2half2_rn(w0.z, w0.w);
    __half2 wh2 = __floats2half2_rn(w1.x, w1.y);
    __half2 wh3 = __floats2half2_rn(w1.z, w1.w);
    float  b2v = b2[0];

    int gw = (blockIdx.x * blockDim.x + threadIdx.x) >> 5;
    int warps = (gridDim.x * blockDim.x) >> 5;

    const __half2 zero2 = __float2half2_rn(0.f);

    for (int e0 = gw * 8; e0 < E; e0 += warps * 8) {
        int eA = e0 + q;
        int eB = e0 + 4 + q;
        bool vA = (eA < E);
        bool vB = (eB < E);

        int rA = vA ? idx[eA]     : 0;
        int cA = vA ? idx[E + eA] : 0;
        int rB = vB ? idx[eB]     : 0;
        int cB = vB ? idx[E + eB] : 0;

        // 4 independent 16B gathers per thread
        uint4 uA = *(const uint4*)(g_U + (size_t)rA * HID + l8 * 8);
        uint4 bA = *(const uint4*)(g_B + (size_t)cA * HID + l8 * 8);
        uint4 uB = *(const uint4*)(g_U + (size_t)rB * HID + l8 * 8);
        uint4 bB = *(const uint4*)(g_B + (size_t)cB * HID + l8 * 8);

        float pA, pB;
        {
            const __half2* u = (const __half2*)&uA;
            const __half2* b = (const __half2*)&bA;
            __half2 h0 = __hmax2(__hadd2(u[0], b[0]), zero2);
            __half2 h1 = __hmax2(__hadd2(u[1], b[1]), zero2);
            __half2 h2 = __hmax2(__hadd2(u[2], b[2]), zero2);
            __half2 h3 = __hmax2(__hadd2(u[3], b[3]), zero2);
            __half2 a = __hmul2(h0, wh0);
            a = __hfma2(h1, wh1, a);
            a = __hfma2(h2, wh2, a);
            a = __hfma2(h3, wh3, a);
            float2 f = __half22float2(a);
            pA = f.x + f.y;
        }
        {
            const __half2* u = (const __half2*)&uB;
            const __half2* b = (const __half2*)&bB;
            __half2 h0 = __hmax2(__hadd2(u[0], b[0]), zero2);
            __half2 h1 = __hmax2(__hadd2(u[1], b[1]), zero2);
            __half2 h2 = __hmax2(__hadd2(u[2], b[2]), zero2);
            __half2 h3 = __hmax2(__hadd2(u[3], b[3]), zero2);
            __half2 a = __hmul2(h0, wh0);
            a = __hfma2(h1, wh1, a);
            a = __hfma2(h2, wh2, a);
            a = __hfma2(h3, wh3, a);
            float2 f = __half22float2(a);
            pB = f.x + f.y;
        }

        pA += __shfl_xor_sync(0xffffffffu, pA, 1);
        pB += __shfl_xor_sync(0xffffffffu, pB, 1);
        pA += __shfl_xor_sync(0xffffffffu, pA, 2);
        pB += __shfl_xor_sync(0xffffffffu, pB, 2);
        pA += __shfl_xor_sync(0xffffffffu, pA, 4);
        pB += __shfl_xor_sync(0xffffffffu, pB, 4);

        if (l8 == 0) {
            if (vA) out[eA] = pA + b2v;
            if (vB) out[eB] = pB + b2v;
        }
    }
}

// ---------------------------------------------------------------------------
extern "C" void kernel_launch(void* const* d_in, const int* in_sizes, int n_in,
                              void* d_out, int out_size)
{
    const float* z_user  = (const float*)d_in[0];
    const float* z_books = (const float*)d_in[1];
    const int*   idx     = (const int*)d_in[2];
    const float* W1      = (const float*)d_in[3];
    const float* b1      = (const float*)d_in[4];
    const float* W2      = (const float*)d_in[5];
    const float* b2      = (const float*)d_in[6];
    float*       out     = (float*)d_out;

    int E = in_sizes[2] / 2;             // edge_label_index is [2, E]

    // Phase 1: 12500 warp-tiles, 8 warps/block -> 1563 blocks
    precompute_mma<<<(WTILES_TOTAL + 7) / 8, 256>>>(z_user, z_books, W1, b1);

    // Phase 2: grid-stride; 16384 warps * 8 edges per trip
    edge_kernel<<<2048, 256>>>(idx, W2, b2, out, E);
}

// round 10
// speedup vs baseline: 2.3110x; 1.0576x over previous
#include <cuda_runtime.h>
#include <cuda_fp16.h>
#include <cstdint>

#define NUM_NODES 100000
#define HID 64
#define WTILES_PER_HALF (NUM_NODES / 16)      // 6250 warp-tiles per table
#define WTILES_TOTAL (2 * WTILES_PER_HALF)    // 12500

// Scratch tables in fp16 (allocation-free rule: __device__ globals).
__device__ __half g_U[NUM_NODES * HID];
__device__ __half g_B[NUM_NODES * HID];

// Pre-converted, pre-swizzled W1 in fp16 B-fragment layout:
// uint2 entry per (half, jt, ks, g, tc):
//   .x = half2(W[j][k2=ks*8+tc]),  .y = half2(W[j][k2=ks*8+tc+4]),  j=jt*8+g
// index = (((half*8 + jt)*4 + ks)*8 + g)*4 + tc     (2048 entries, 16 KB)
__device__ uint32_t g_Wq[4096];

__device__ __forceinline__ uint32_t f2h2(float x, float y) {
    __half2 h = __floats2half2_rn(x, y);
    return *reinterpret_cast<uint32_t*>(&h);
}
__device__ __forceinline__ void mma_f16(float* c, uint32_t a0, uint32_t a1,
                                        uint32_t a2, uint32_t a3,
                                        uint32_t b0, uint32_t b1) {
    asm volatile(
        "mma.sync.aligned.m16n8k16.row.col.f32.f16.f16.f32 "
        "{%0,%1,%2,%3}, {%4,%5,%6,%7}, {%8,%9}, {%0,%1,%2,%3};"
        : "+f"(c[0]), "+f"(c[1]), "+f"(c[2]), "+f"(c[3])
        : "r"(a0), "r"(a1), "r"(a2), "r"(a3), "r"(b0), "r"(b1));
}

// ---------------------------------------------------------------------------
// Setup: one block converts W1 -> fp16 fragment layout in g_Wq (runs once per
// launch; ~4096 elements, trivial).
// ---------------------------------------------------------------------------
__global__ __launch_bounds__(256) void setup_w(const float* __restrict__ W1)
{
    for (int i = threadIdx.x; i < 4096; i += 256) {
        int half = i >> 11;              // 0 = user cols, 1 = book cols
        int j    = (i >> 5) & 63;
        int k2   = i & 31;
        float2 w = *(const float2*)(W1 + j * 128 + half * 64 + k2 * 2);
        int jt = j >> 3, g = j & 7;
        int ks = k2 >> 3, t = k2 & 7, tc = t & 3, sel = t >> 2;
        int entry = (((half * 8 + jt) * 4 + ks) * 8 + g) * 4 + tc;
        g_Wq[entry * 2 + sel] = f2h2(w.x, w.y);
    }
}

// ---------------------------------------------------------------------------
// Phase 1: single-pass fp16 HMMA GEMM (fp32 accumulate, fp16 store).
// One warp = 16 nodes x 64 outputs, K=64 -> 8 jt x 4 ks = 32 MMAs.
// Warp-tiles [0,6250) -> U (+b1), rest -> B.
// ---------------------------------------------------------------------------
__global__ __launch_bounds__(256) void precompute_mma(
    const float* __restrict__ z_user,
    const float* __restrict__ z_books,
    const float* __restrict__ b1)    // [64]
{
    __shared__ uint32_t Wq[4096];    // 16 KB copy of g_Wq
    __shared__ float b1s[64];

    int tid = threadIdx.x;
    // 4 x LDG.128/STS.128 per thread
    #pragma unroll
    for (int i = 0; i < 4; i++) {
        int o = (i * 256 + tid) * 4;
        *(uint4*)(Wq + o) = *(const uint4*)(g_Wq + o);
    }
    if (tid < 64) b1s[tid] = b1[tid];
    __syncthreads();

    int wid = tid >> 5, lane = tid & 31;
    int wt = blockIdx.x * 8 + wid;
    if (wt >= WTILES_TOTAL) return;

    bool isU = (wt < WTILES_PER_HALF);
    int tile = isU ? wt : wt - WTILES_PER_HALF;
    int nb = tile * 16;
    const float* z = isU ? z_user : z_books;
    int half = isU ? 0 : 1;

    int g = lane >> 2, tc = lane & 3;

    const float2* zr0 = (const float2*)(z + (size_t)(nb + g) * HID);
    const float2* zr1 = (const float2*)(z + (size_t)(nb + g + 8) * HID);

    float acc[8][4];
    #pragma unroll
    for (int jt = 0; jt < 8; jt++)
        #pragma unroll
        for (int c = 0; c < 4; c++) acc[jt][c] = 0.f;

    #pragma unroll
    for (int ks = 0; ks < 4; ks++) {
        // A fragments: rows g / g+8, k pairs (ks*16+tc*2, +1) and (+8, +9)
        float2 p00 = zr0[ks * 8 + tc],     p02 = zr0[ks * 8 + tc + 4];
        float2 p10 = zr1[ks * 8 + tc],     p12 = zr1[ks * 8 + tc + 4];
        uint32_t a0 = f2h2(p00.x, p00.y);
        uint32_t a1 = f2h2(p10.x, p10.y);
        uint32_t a2 = f2h2(p02.x, p02.y);
        uint32_t a3 = f2h2(p12.x, p12.y);

        #pragma unroll
        for (int jt = 0; jt < 8; jt++) {
            int entry = (((half * 8 + jt) * 4 + ks) * 8 + g) * 4 + tc;
            uint2 b = *(const uint2*)(Wq + entry * 2);   // conflict-free LDS.64
            mma_f16(acc[jt], a0, a1, a2, a3, b.x, b.y);
        }
    }

    // Epilogue: (c0,c1) -> row g cols (2n2, 2n2+1); (c2,c3) -> row g+8.
    __half* table = isU ? g_U : g_B;
    __half2* o0 = (__half2*)(table + (size_t)(nb + g) * HID);
    __half2* o1 = (__half2*)(table + (size_t)(nb + g + 8) * HID);
    #pragma unroll
    for (int jt = 0; jt < 8; jt++) {
        int n2 = jt * 4 + tc;            // half2 column index (col = 2*n2)
        float bx = 0.f, by = 0.f;
        if (isU) { bx = b1s[2 * n2]; by = b1s[2 * n2 + 1]; }
        o0[n2] = __floats2half2_rn(acc[jt][0] + bx, acc[jt][1] + by);
        o1[n2] = __floats2half2_rn(acc[jt][2] + bx, acc[jt][3] + by);
    }
}

// ---------------------------------------------------------------------------
// Phase 2: per-edge decode on fp16 tables — at the ~12 TB/s LTS roofline.
// 8 lanes/edge, 8 edges/warp/trip, half2 math, fp32 shuffle reduce.
// Edge pairs are adjacent -> int2 idx loads, float2 output store.
// ---------------------------------------------------------------------------
__global__ __launch_bounds__(256) void edge_kernel(
    const int* __restrict__ idx,         // [2][E] int32
    const float* __restrict__ W2,        // [1][64]
    const float* __restrict__ b2,        // [1]
    float* __restrict__ out,             // [E]
    int E)
{
    int lane = threadIdx.x & 31;
    int q  = lane >> 3;                  // edge-pair slot (0..3)
    int l8 = lane & 7;                   // feature chunk: 8 halves per lane

    float4 w0 = ((const float4*)W2)[2 * l8];
    float4 w1 = ((const float4*)W2)[2 * l8 + 1];
    __half2 wh0 = __floats2half2_rn(w0.x, w0.y);
    __half2 wh1 = __floats2half2_rn(w0.z, w0.w);
    __half2 wh2 = __floats2half2_rn(w1.x, w1.y);
    __half2 wh3 = __floats2half2_rn(w1.z, w1.w);
    float  b2v = b2[0];

    int gw = (blockIdx.x * blockDim.x + threadIdx.x) >> 5;
    int warps = (gridDim.x * blockDim.x) >> 5;

    const __half2 zero2 = __float2half2_rn(0.f);

    for (int e0 = gw * 8; e0 < E; e0 += warps * 8) {
        int eA = e0 + 2 * q;             // eB = eA + 1; E even -> both valid
        bool v = (eA < E);

        int2 rc = v ? *(const int2*)(idx + eA)     : make_int2(0, 0);
        int2 cc = v ? *(const int2*)(idx + E + eA) : make_int2(0, 0);

        // 4 independent 16B gathers per thread
        uint4 uA = *(const uint4*)(g_U + (size_t)rc.x * HID + l8 * 8);
        uint4 bA = *(const uint4*)(g_B + (size_t)cc.x * HID + l8 * 8);
        uint4 uB = *(const uint4*)(g_U + (size_t)rc.y * HID + l8 * 8);
        uint4 bB = *(const uint4*)(g_B + (size_t)cc.y * HID + l8 * 8);

        float pA, pB;
        {
            const __half2* u = (const __half2*)&uA;
            const __half2* b = (const __half2*)&bA;
            __half2 h0 = __hmax2(__hadd2(u[0], b[0]), zero2);
            __half2 h1 = __hmax2(__hadd2(u[1], b[1]), zero2);
            __half2 h2 = __hmax2(__hadd2(u[2], b[2]), zero2);
            __half2 h3 = __hmax2(__hadd2(u[3], b[3]), zero2);
            __half2 a = __hmul2(h0, wh0);
            a = __hfma2(h1, wh1, a);
            a = __hfma2(h2, wh2, a);
            a = __hfma2(h3, wh3, a);
            float2 f = __half22float2(a);
            pA = f.x + f.y;
        }
        {
            const __half2* u = (const __half2*)&uB;
            const __half2* b = (const __half2*)&bB;
            __half2 h0 = __hmax2(__hadd2(u[0], b[0]), zero2);
            __half2 h1 = __hmax2(__hadd2(u[1], b[1]), zero2);
            __half2 h2 = __hmax2(__hadd2(u[2], b[2]), zero2);
            __half2 h3 = __hmax2(__hadd2(u[3], b[3]), zero2);
            __half2 a = __hmul2(h0, wh0);
            a = __hfma2(h1, wh1, a);
            a = __hfma2(h2, wh2, a);
            a = __hfma2(h3, wh3, a);
            float2 f = __half22float2(a);
            pB = f.x + f.y;
        }

        pA += __shfl_xor_sync(0xffffffffu, pA, 1);
        pB += __shfl_xor_sync(0xffffffffu, pB, 1);
        pA += __shfl_xor_sync(0xffffffffu, pA, 2);
        pB += __shfl_xor_sync(0xffffffffu, pB, 2);
        pA += __shfl_xor_sync(0xffffffffu, pA, 4);
        pB += __shfl_xor_sync(0xffffffffu, pB, 4);

        if (l8 == 0 && v)
            *(float2*)(out + eA) = make_float2(pA + b2v, pB + b2v);
    }
}

// ---------------------------------------------------------------------------
extern "C" void kernel_launch(void* const* d_in, const int* in_sizes, int n_in,
                              void* d_out, int out_size)
{
    const float* z_user  = (const float*)d_in[0];
    const float* z_books = (const float*)d_in[1];
    const int*   idx     = (const int*)d_in[2];
    const float* W1      = (const float*)d_in[3];
    const float* b1      = (const float*)d_in[4];
    const float* W2      = (const float*)d_in[5];
    const float* b2      = (const float*)d_in[6];
    float*       out     = (float*)d_out;

    int E = in_sizes[2] / 2;             // edge_label_index is [2, E]

    setup_w<<<1, 256>>>(W1);
    precompute_mma<<<(WTILES_TOTAL + 7) / 8, 256>>>(z_user, z_books, b1);
    edge_kernel<<<2048, 256>>>(idx, W2, b2, out, E);
}

// round 11
// speedup vs baseline: 2.3790x; 1.0294x over previous
#include <cuda_runtime.h>
#include <cuda_fp16.h>
#include <cstdint>

#define NUM_NODES 100000
#define HID 64
#define WTILES_PER_HALF (NUM_NODES / 16)      // 6250 warp-tiles per table
#define WTILES_TOTAL (2 * WTILES_PER_HALF)    // 12500

// Scratch tables in fp16 (allocation-free rule: __device__ globals).
__device__ __half g_U[NUM_NODES * HID];
__device__ __half g_B[NUM_NODES * HID];

__device__ __forceinline__ uint32_t f2h2(float x, float y) {
    __half2 h = __floats2half2_rn(x, y);
    return *reinterpret_cast<uint32_t*>(&h);
}
__device__ __forceinline__ void mma_f16(float* c, uint32_t a0, uint32_t a1,
                                        uint32_t a2, uint32_t a3,
                                        uint32_t b0, uint32_t b1) {
    asm volatile(
        "mma.sync.aligned.m16n8k16.row.col.f32.f16.f16.f32 "
        "{%0,%1,%2,%3}, {%4,%5,%6,%7}, {%8,%9}, {%0,%1,%2,%3};"
        : "+f"(c[0]), "+f"(c[1]), "+f"(c[2]), "+f"(c[3])
        : "r"(a0), "r"(a1), "r"(a2), "r"(a3), "r"(b0), "r"(b1));
}

// ---------------------------------------------------------------------------
// Phase 1: single-pass fp16 HMMA GEMM (fp32 accumulate, fp16 store).
// W1 is converted to fragment layout in-block (smem), no setup kernel:
//   uint2 entry per (half, jt, ks, g, tc):
//     .x = half2(W[j][k2=ks*8+tc]), .y = half2(W[j][k2=ks*8+tc+4]), j=jt*8+g
//   entry = (((half*8 + jt)*4 + ks)*8 + g)*4 + tc   (2048 entries, 16 KB)
// One warp = 16 nodes x 64 outputs, K=64 -> 8 jt x 4 ks = 32 MMAs.
// Warp-tiles [0,6250) -> U (+b1), rest -> B.
// ---------------------------------------------------------------------------
__global__ __launch_bounds__(256) void precompute_mma(
    const float* __restrict__ z_user,
    const float* __restrict__ z_books,
    const float* __restrict__ W1,    // [64][128]
    const float* __restrict__ b1)    // [64]
{
    __shared__ uint32_t Wq[4096];    // 16 KB fragment-layout W
    __shared__ float b1s[64];

    int tid = threadIdx.x;
    #pragma unroll
    for (int it = 0; it < 16; it++) {
        int i = it * 256 + tid;          // linear element 0..4095
        int half = i >> 11;              // 0 = user cols, 1 = book cols
        int j    = (i >> 5) & 63;
        int k2   = i & 31;
        float2 w = *(const float2*)(W1 + j * 128 + half * 64 + k2 * 2);
        int jt = j >> 3, g = j & 7;
        int ks = k2 >> 3, t = k2 & 7, tc = t & 3, sel = t >> 2;
        int entry = (((half * 8 + jt) * 4 + ks) * 8 + g) * 4 + tc;
        Wq[entry * 2 + sel] = f2h2(w.x, w.y);
    }
    if (tid < 64) b1s[tid] = b1[tid];
    __syncthreads();

    int wid = tid >> 5, lane = tid & 31;
    int wt = blockIdx.x * 8 + wid;
    if (wt >= WTILES_TOTAL) return;

    bool isU = (wt < WTILES_PER_HALF);
    int tile = isU ? wt : wt - WTILES_PER_HALF;
    int nb = tile * 16;
    const float* z = isU ? z_user : z_books;
    int half = isU ? 0 : 1;

    int g = lane >> 2, tc = lane & 3;

    const float2* zr0 = (const float2*)(z + (size_t)(nb + g) * HID);
    const float2* zr1 = (const float2*)(z + (size_t)(nb + g + 8) * HID);

    float acc[8][4];
    #pragma unroll
    for (int jt = 0; jt < 8; jt++)
        #pragma unroll
        for (int c = 0; c < 4; c++) acc[jt][c] = 0.f;

    #pragma unroll
    for (int ks = 0; ks < 4; ks++) {
        // A fragments: rows g / g+8, k pairs (ks*16+tc*2, +1) and (+8, +9)
        float2 p00 = zr0[ks * 8 + tc],     p02 = zr0[ks * 8 + tc + 4];
        float2 p10 = zr1[ks * 8 + tc],     p12 = zr1[ks * 8 + tc + 4];
        uint32_t a0 = f2h2(p00.x, p00.y);
        uint32_t a1 = f2h2(p10.x, p10.y);
        uint32_t a2 = f2h2(p02.x, p02.y);
        uint32_t a3 = f2h2(p12.x, p12.y);

        #pragma unroll
        for (int jt = 0; jt < 8; jt++) {
            int entry = (((half * 8 + jt) * 4 + ks) * 8 + g) * 4 + tc;
            uint2 b = *(const uint2*)(Wq + entry * 2);   // conflict-free LDS.64
            mma_f16(acc[jt], a0, a1, a2, a3, b.x, b.y);
        }
    }

    // Epilogue: (c0,c1) -> row g cols (2n2, 2n2+1); (c2,c3) -> row g+8.
    __half* table = isU ? g_U : g_B;
    __half2* o0 = (__half2*)(table + (size_t)(nb + g) * HID);
    __half2* o1 = (__half2*)(table + (size_t)(nb + g + 8) * HID);
    #pragma unroll
    for (int jt = 0; jt < 8; jt++) {
        int n2 = jt * 4 + tc;            // half2 column index (col = 2*n2)
        float bx = 0.f, by = 0.f;
        if (isU) { bx = b1s[2 * n2]; by = b1s[2 * n2 + 1]; }
        o0[n2] = __floats2half2_rn(acc[jt][0] + bx, acc[jt][1] + by);
        o1[n2] = __floats2half2_rn(acc[jt][2] + bx, acc[jt][3] + by);
    }
}

// ---------------------------------------------------------------------------
// Phase 2: per-edge decode on fp16 tables — at the ~12 TB/s LTS roofline.
// 8 lanes/edge, 8 edges/warp/trip, half2 math, fp32 shuffle reduce.
// Edge pairs are adjacent -> int2 idx loads, float2 output store.
// ---------------------------------------------------------------------------
__global__ __launch_bounds__(256) void edge_kernel(
    const int* __restrict__ idx,         // [2][E] int32
    const float* __restrict__ W2,        // [1][64]
    const float* __restrict__ b2,        // [1]
    float* __restrict__ out,             // [E]
    int E)
{
    int lane = threadIdx.x & 31;
    int q  = lane >> 3;                  // edge-pair slot (0..3)
    int l8 = lane & 7;                   // feature chunk: 8 halves per lane

    float4 w0 = ((const float4*)W2)[2 * l8];
    float4 w1 = ((const float4*)W2)[2 * l8 + 1];
    __half2 wh0 = __floats2half2_rn(w0.x, w0.y);
    __half2 wh1 = __floats2half2_rn(w0.z, w0.w);
    __half2 wh2 = __floats2half2_rn(w1.x, w1.y);
    __half2 wh3 = __floats2half2_rn(w1.z, w1.w);
    float  b2v = b2[0];

    int gw = (blockIdx.x * blockDim.x + threadIdx.x) >> 5;
    int warps = (gridDim.x * blockDim.x) >> 5;

    const __half2 zero2 = __float2half2_rn(0.f);

    for (int e0 = gw * 8; e0 < E; e0 += warps * 8) {
        int eA = e0 + 2 * q;             // eB = eA + 1; E even -> both valid
        bool v = (eA < E);

        int2 rc = v ? *(const int2*)(idx + eA)     : make_int2(0, 0);
        int2 cc = v ? *(const int2*)(idx + E + eA) : make_int2(0, 0);

        // 4 independent 16B gathers per thread
        uint4 uA = *(const uint4*)(g_U + (size_t)rc.x * HID + l8 * 8);
        uint4 bA = *(const uint4*)(g_B + (size_t)cc.x * HID + l8 * 8);
        uint4 uB = *(const uint4*)(g_U + (size_t)rc.y * HID + l8 * 8);
        uint4 bB = *(const uint4*)(g_B + (size_t)cc.y * HID + l8 * 8);

        float pA, pB;
        {
            const __half2* u = (const __half2*)&uA;
            const __half2* b = (const __half2*)&bA;
            __half2 h0 = __hmax2(__hadd2(u[0], b[0]), zero2);
            __half2 h1 = __hmax2(__hadd2(u[1], b[1]), zero2);
            __half2 h2 = __hmax2(__hadd2(u[2], b[2]), zero2);
            __half2 h3 = __hmax2(__hadd2(u[3], b[3]), zero2);
            __half2 a = __hmul2(h0, wh0);
            a = __hfma2(h1, wh1, a);
            a = __hfma2(h2, wh2, a);
            a = __hfma2(h3, wh3, a);
            float2 f = __half22float2(a);
            pA = f.x + f.y;
        }
        {
            const __half2* u = (const __half2*)&uB;
            const __half2* b = (const __half2*)&bB;
            __half2 h0 = __hmax2(__hadd2(u[0], b[0]), zero2);
            __half2 h1 = __hmax2(__hadd2(u[1], b[1]), zero2);
            __half2 h2 = __hmax2(__hadd2(u[2], b[2]), zero2);
            __half2 h3 = __hmax2(__hadd2(u[3], b[3]), zero2);
            __half2 a = __hmul2(h0, wh0);
            a = __hfma2(h1, wh1, a);
            a = __hfma2(h2, wh2, a);
            a = __hfma2(h3, wh3, a);
            float2 f = __half22float2(a);
            pB = f.x + f.y;
        }

        pA += __shfl_xor_sync(0xffffffffu, pA, 1);
        pB += __shfl_xor_sync(0xffffffffu, pB, 1);
        pA += __shfl_xor_sync(0xffffffffu, pA, 2);
        pB += __shfl_xor_sync(0xffffffffu, pB, 2);
        pA += __shfl_xor_sync(0xffffffffu, pA, 4);
        pB += __shfl_xor_sync(0xffffffffu, pB, 4);

        if (l8 == 0 && v)
            *(float2*)(out + eA) = make_float2(pA + b2v, pB + b2v);
    }
}

// ---------------------------------------------------------------------------
extern "C" void kernel_launch(void* const* d_in, const int* in_sizes, int n_in,
                              void* d_out, int out_size)
{
    const float* z_user  = (const float*)d_in[0];
    const float* z_books = (const float*)d_in[1];
    const int*   idx     = (const int*)d_in[2];
    const float* W1      = (const float*)d_in[3];
    const float* b1      = (const float*)d_in[4];
    const float* W2      = (const float*)d_in[5];
    const float* b2      = (const float*)d_in[6];
    float*       out     = (float*)d_out;

    int E = in_sizes[2] / 2;             // edge_label_index is [2, E]

    // Phase 1: 12500 warp-tiles, 8 warps/block -> 1563 blocks
    precompute_mma<<<(WTILES_TOTAL + 7) / 8, 256>>>(z_user, z_books, W1, b1);

    // Phase 2: grid-stride; 16384 warps * 8 edges per trip
    edge_kernel<<<2048, 256>>>(idx, W2, b2, out, E);
}

// round 12
// speedup vs baseline: 2.7398x; 1.1516x over previous
#include <cuda_runtime.h>
#include <cuda_fp16.h>
#include <cstdint>

#define NUM_NODES 100000
#define HID 64
#define WTILES_PER_HALF (NUM_NODES / 16)      // 6250 warp-tiles per table
#define WTILES_TOTAL (2 * WTILES_PER_HALF)    // 12500
#define PRE_BLOCKS 782                        // 6256 warps -> 2 tiles/warp

// Scratch tables in fp16 (allocation-free rule: __device__ globals).
__device__ __half g_U[NUM_NODES * HID];
__device__ __half g_B[NUM_NODES * HID];

__device__ __forceinline__ uint32_t f2h2(float x, float y) {
    __half2 h = __floats2half2_rn(x, y);
    return *reinterpret_cast<uint32_t*>(&h);
}
__device__ __forceinline__ void mma_f16(float* c, uint32_t a0, uint32_t a1,
                                        uint32_t a2, uint32_t a3,
                                        uint32_t b0, uint32_t b1) {
    asm volatile(
        "mma.sync.aligned.m16n8k16.row.col.f32.f16.f16.f32 "
        "{%0,%1,%2,%3}, {%4,%5,%6,%7}, {%8,%9}, {%0,%1,%2,%3};"
        : "+f"(c[0]), "+f"(c[1]), "+f"(c[2]), "+f"(c[3])
        : "r"(a0), "r"(a1), "r"(a2), "r"(a3), "r"(b0), "r"(b1));
}

// ---------------------------------------------------------------------------
// Phase 1: single-pass fp16 HMMA GEMM (fp32 accumulate, fp16 store).
// W1 converted to fragment layout in-block (smem) once, then each warp
// grid-strides over 2 warp-tiles. One warp-tile = 16 nodes x 64 outputs,
// K=64 -> 8 jt x 4 ks = 32 MMAs. Tiles [0,6250) -> U (+b1), rest -> B.
// ---------------------------------------------------------------------------
__global__ __launch_bounds__(256) void precompute_mma(
    const float* __restrict__ z_user,
    const float* __restrict__ z_books,
    const float* __restrict__ W1,    // [64][128]
    const float* __restrict__ b1)    // [64]
{
    __shared__ uint32_t Wq[4096];    // 16 KB fragment-layout W
    __shared__ float b1s[64];

    int tid = threadIdx.x;
    #pragma unroll
    for (int it = 0; it < 16; it++) {
        int i = it * 256 + tid;          // linear element 0..4095
        int half = i >> 11;              // 0 = user cols, 1 = book cols
        int j    = (i >> 5) & 63;
        int k2   = i & 31;
        float2 w = *(const float2*)(W1 + j * 128 + half * 64 + k2 * 2);
        int jt = j >> 3, g = j & 7;
        int ks = k2 >> 3, t = k2 & 7, tc = t & 3, sel = t >> 2;
        int entry = (((half * 8 + jt) * 4 + ks) * 8 + g) * 4 + tc;
        Wq[entry * 2 + sel] = f2h2(w.x, w.y);
    }
    if (tid < 64) b1s[tid] = b1[tid];
    __syncthreads();

    int wid = tid >> 5, lane = tid & 31;
    int g = lane >> 2, tc = lane & 3;

    for (int wt = blockIdx.x * 8 + wid; wt < WTILES_TOTAL; wt += PRE_BLOCKS * 8) {
        bool isU = (wt < WTILES_PER_HALF);
        int tile = isU ? wt : wt - WTILES_PER_HALF;
        int nb = tile * 16;
        const float* z = isU ? z_user : z_books;
        int half = isU ? 0 : 1;

        const float2* zr0 = (const float2*)(z + (size_t)(nb + g) * HID);
        const float2* zr1 = (const float2*)(z + (size_t)(nb + g + 8) * HID);

        float acc[8][4];
        #pragma unroll
        for (int jt = 0; jt < 8; jt++)
            #pragma unroll
            for (int c = 0; c < 4; c++) acc[jt][c] = 0.f;

        #pragma unroll
        for (int ks = 0; ks < 4; ks++) {
            // A fragments: rows g / g+8, k pairs (ks*16+tc*2, +1), (+8, +9)
            float2 p00 = zr0[ks * 8 + tc],     p02 = zr0[ks * 8 + tc + 4];
            float2 p10 = zr1[ks * 8 + tc],     p12 = zr1[ks * 8 + tc + 4];
            uint32_t a0 = f2h2(p00.x, p00.y);
            uint32_t a1 = f2h2(p10.x, p10.y);
            uint32_t a2 = f2h2(p02.x, p02.y);
            uint32_t a3 = f2h2(p12.x, p12.y);

            #pragma unroll
            for (int jt = 0; jt < 8; jt++) {
                int entry = (((half * 8 + jt) * 4 + ks) * 8 + g) * 4 + tc;
                uint2 b = *(const uint2*)(Wq + entry * 2);  // conflict-free LDS.64
                mma_f16(acc[jt], a0, a1, a2, a3, b.x, b.y);
            }
        }

        // Epilogue: (c0,c1) -> row g cols (2n2, 2n2+1); (c2,c3) -> row g+8.
        __half* table = isU ? g_U : g_B;
        __half2* o0 = (__half2*)(table + (size_t)(nb + g) * HID);
        __half2* o1 = (__half2*)(table + (size_t)(nb + g + 8) * HID);
        #pragma unroll
        for (int jt = 0; jt < 8; jt++) {
            int n2 = jt * 4 + tc;        // half2 column index (col = 2*n2)
            float bx = 0.f, by = 0.f;
            if (isU) { bx = b1s[2 * n2]; by = b1s[2 * n2 + 1]; }
            o0[n2] = __floats2half2_rn(acc[jt][0] + bx, acc[jt][1] + by);
            o1[n2] = __floats2half2_rn(acc[jt][2] + bx, acc[jt][3] + by);
        }
    }
}

// ---------------------------------------------------------------------------
// Phase 2: per-edge decode on fp16 tables — at the ~12 TB/s LTS roofline.
// R9 form (measured 45.8 us, regs=32, occ=84%): 8 lanes/edge, two separate
// edge slots eA/eB per trip, scalar idx loads, scalar stores, half2 math,
// fp32 shuffle reduce. launch_bounds(256,8) pins 32 regs / full residency.
// ---------------------------------------------------------------------------
__global__ void __launch_bounds__(256, 8) edge_kernel(
    const int* __restrict__ idx,         // [2][E] int32
    const float* __restrict__ W2,        // [1][64]
    const float* __restrict__ b2,        // [1]
    float* __restrict__ out,             // [E]
    int E)
{
    int lane = threadIdx.x & 31;
    int q  = lane >> 3;                  // edge slot within warp-pass (0..3)
    int l8 = lane & 7;                   // feature chunk: 8 halves per lane

    float4 w0 = ((const float4*)W2)[2 * l8];
    float4 w1 = ((const float4*)W2)[2 * l8 + 1];
    __half2 wh0 = __floats2half2_rn(w0.x, w0.y);
    __half2 wh1 = __floats2half2_rn(w0.z, w0.w);
    __half2 wh2 = __floats2half2_rn(w1.x, w1.y);
    __half2 wh3 = __floats2half2_rn(w1.z, w1.w);
    float  b2v = b2[0];

    int gw = (blockIdx.x * blockDim.x + threadIdx.x) >> 5;
    int warps = (gridDim.x * blockDim.x) >> 5;

    const __half2 zero2 = __float2half2_rn(0.f);

    for (int e0 = gw * 8; e0 < E; e0 += warps * 8) {
        int eA = e0 + q;
        int eB = e0 + 4 + q;
        bool vA = (eA < E);
        bool vB = (eB < E);

        int rA = vA ? idx[eA]     : 0;
        int cA = vA ? idx[E + eA] : 0;
        int rB = vB ? idx[eB]     : 0;
        int cB = vB ? idx[E + eB] : 0;

        // 4 independent 16B gathers per thread
        uint4 uA = *(const uint4*)(g_U + (size_t)rA * HID + l8 * 8);
        uint4 bA = *(const uint4*)(g_B + (size_t)cA * HID + l8 * 8);
        uint4 uB = *(const uint4*)(g_U + (size_t)rB * HID + l8 * 8);
        uint4 bB = *(const uint4*)(g_B + (size_t)cB * HID + l8 * 8);

        float pA, pB;
        {
            const __half2* u = (const __half2*)&uA;
            const __half2* b = (const __half2*)&bA;
            __half2 h0 = __hmax2(__hadd2(u[0], b[0]), zero2);
            __half2 h1 = __hmax2(__hadd2(u[1], b[1]), zero2);
            __half2 h2 = __hmax2(__hadd2(u[2], b[2]), zero2);
            __half2 h3 = __hmax2(__hadd2(u[3], b[3]), zero2);
            __half2 a = __hmul2(h0, wh0);
            a = __hfma2(h1, wh1, a);
            a = __hfma2(h2, wh2, a);
            a = __hfma2(h3, wh3, a);
            float2 f = __half22float2(a);
            pA = f.x + f.y;
        }
        {
            const __half2* u = (const __half2*)&uB;
            const __half2* b = (const __half2*)&bB;
            __half2 h0 = __hmax2(__hadd2(u[0], b[0]), zero2);
            __half2 h1 = __hmax2(__hadd2(u[1], b[1]), zero2);
            __half2 h2 = __hmax2(__hadd2(u[2], b[2]), zero2);
            __half2 h3 = __hmax2(__hadd2(u[3], b[3]), zero2);
            __half2 a = __hmul2(h0, wh0);
            a = __hfma2(h1, wh1, a);
            a = __hfma2(h2, wh2, a);
            a = __hfma2(h3, wh3, a);
            float2 f = __half22float2(a);
            pB = f.x + f.y;
        }

        pA += __shfl_xor_sync(0xffffffffu, pA, 1);
        pB += __shfl_xor_sync(0xffffffffu, pB, 1);
        pA += __shfl_xor_sync(0xffffffffu, pA, 2);
        pB += __shfl_xor_sync(0xffffffffu, pB, 2);
        pA += __shfl_xor_sync(0xffffffffu, pA, 4);
        pB += __shfl_xor_sync(0xffffffffu, pB, 4);

        if (l8 == 0) {
            if (vA) out[eA] = pA + b2v;
            if (vB) out[eB] = pB + b2v;
        }
    }
}

// ---------------------------------------------------------------------------
extern "C" void kernel_launch(void* const* d_in, const int* in_sizes, int n_in,
                              void* d_out, int out_size)
{
    const float* z_user  = (const float*)d_in[0];
    const float* z_books = (const float*)d_in[1];
    const int*   idx     = (const int*)d_in[2];
    const float* W1      = (const float*)d_in[3];
    const float* b1      = (const float*)d_in[4];
    const float* W2      = (const float*)d_in[5];
    const float* b2      = (const float*)d_in[6];
    float*       out     = (float*)d_out;

    int E = in_sizes[2] / 2;             // edge_label_index is [2, E]

    // Phase 1: grid-stride, 2 warp-tiles per warp
    precompute_mma<<<PRE_BLOCKS, 256>>>(z_user, z_books, W1, b1);

    // Phase 2: grid-stride; 16384 warps * 8 edges per trip
    edge_kernel<<<2048, 256>>>(idx, W2, b2, out, E);
}

// round 13
// speedup vs baseline: 3.0080x; 1.0979x over previous
#include <cuda_runtime.h>
#include <cuda_fp16.h>
#include <cstdint>

#define NUM_NODES 100000
#define HID 64
#define WTILES_PER_HALF (NUM_NODES / 16)      // 6250 warp-tiles per table
#define WTILES_TOTAL (2 * WTILES_PER_HALF)    // 12500
#define PRE_BLOCKS 782                        // 6256 warps -> 2 tiles/warp
#define EDGE_BLOCKS 1184                      // 148 SMs x 8 CTAs: single wave

// Scratch tables in fp16 (allocation-free rule: __device__ globals).
__device__ __half g_U[NUM_NODES * HID];
__device__ __half g_B[NUM_NODES * HID];

__device__ __forceinline__ uint32_t f2h2(float x, float y) {
    __half2 h = __floats2half2_rn(x, y);
    return *reinterpret_cast<uint32_t*>(&h);
}
__device__ __forceinline__ void mma_f16(float* c, uint32_t a0, uint32_t a1,
                                        uint32_t a2, uint32_t a3,
                                        uint32_t b0, uint32_t b1) {
    asm volatile(
        "mma.sync.aligned.m16n8k16.row.col.f32.f16.f16.f32 "
        "{%0,%1,%2,%3}, {%4,%5,%6,%7}, {%8,%9}, {%0,%1,%2,%3};"
        : "+f"(c[0]), "+f"(c[1]), "+f"(c[2]), "+f"(c[3])
        : "r"(a0), "r"(a1), "r"(a2), "r"(a3), "r"(b0), "r"(b1));
}

// ---------------------------------------------------------------------------
// Phase 1: single-pass fp16 HMMA GEMM (fp32 accumulate, fp16 store).
// Output-column permutation: MMA jt covers actual cols {16q+2jt(+1), q=0..3},
// i.e. actual col j sits in MMA jt=(j&15)>>1 at fragment slot f=2*(j>>4)+(j&1).
// Lane tc then owns contiguous half2 cols n2 = 8tc+jt -> epilogue is
// 4 coalesced STG.128 per thread instead of 16 scattered STG.32.
// One warp-tile = 16 nodes x 64 outputs, K=64 -> 8 jt x 4 ks = 32 MMAs.
// Tiles [0,6250) -> U (+b1), rest -> B. 2 tiles per warp (grid-stride).
// ---------------------------------------------------------------------------
__global__ __launch_bounds__(256) void precompute_mma(
    const float* __restrict__ z_user,
    const float* __restrict__ z_books,
    const float* __restrict__ W1,    // [64][128]
    const float* __restrict__ b1)    // [64]
{
    __shared__ uint32_t Wq[4096];    // 16 KB fragment-layout W
    __shared__ float b1s[64];

    int tid = threadIdx.x;
    #pragma unroll
    for (int it = 0; it < 16; it++) {
        int i = it * 256 + tid;          // linear element 0..4095
        int half = i >> 11;              // 0 = user cols, 1 = book cols
        int j    = (i >> 5) & 63;
        int k2   = i & 31;
        float2 w = *(const float2*)(W1 + j * 128 + half * 64 + k2 * 2);
        int jt = (j & 15) >> 1;          // permuted MMA index
        int f  = 2 * (j >> 4) + (j & 1); // fragment n-slot
        int ks = k2 >> 3, t = k2 & 7, tc = t & 3, sel = t >> 2;
        int entry = (((half * 8 + jt) * 4 + ks) * 8 + f) * 4 + tc;
        Wq[entry * 2 + sel] = f2h2(w.x, w.y);
    }
    if (tid < 64) b1s[tid] = b1[tid];
    __syncthreads();

    int wid = tid >> 5, lane = tid & 31;
    int g = lane >> 2, tc = lane & 3;

    for (int wt = blockIdx.x * 8 + wid; wt < WTILES_TOTAL; wt += PRE_BLOCKS * 8) {
        bool isU = (wt < WTILES_PER_HALF);
        int tile = isU ? wt : wt - WTILES_PER_HALF;
        int nb = tile * 16;
        const float* z = isU ? z_user : z_books;
        int half = isU ? 0 : 1;

        const float2* zr0 = (const float2*)(z + (size_t)(nb + g) * HID);
        const float2* zr1 = (const float2*)(z + (size_t)(nb + g + 8) * HID);

        float acc[8][4];
        #pragma unroll
        for (int jt = 0; jt < 8; jt++)
            #pragma unroll
            for (int c = 0; c < 4; c++) acc[jt][c] = 0.f;

        #pragma unroll
        for (int ks = 0; ks < 4; ks++) {
            // A fragments: rows g / g+8, k pairs (ks*16+tc*2, +1), (+8, +9)
            float2 p00 = zr0[ks * 8 + tc],     p02 = zr0[ks * 8 + tc + 4];
            float2 p10 = zr1[ks * 8 + tc],     p12 = zr1[ks * 8 + tc + 4];
            uint32_t a0 = f2h2(p00.x, p00.y);
            uint32_t a1 = f2h2(p10.x, p10.y);
            uint32_t a2 = f2h2(p02.x, p02.y);
            uint32_t a3 = f2h2(p12.x, p12.y);

            #pragma unroll
            for (int jt = 0; jt < 8; jt++) {
                int entry = (((half * 8 + jt) * 4 + ks) * 8 + g) * 4 + tc;
                uint2 b = *(const uint2*)(Wq + entry * 2);  // conflict-free LDS.64
                mma_f16(acc[jt], a0, a1, a2, a3, b.x, b.y);
            }
        }

        // Epilogue: lane (g,tc) owns rows g/g+8, half2 cols 8tc+jt (jt=0..7).
        __half* table = isU ? g_U : g_B;
        uint32_t h0[8], h1[8];
        #pragma unroll
        for (int jt = 0; jt < 8; jt++) {
            int c0 = 16 * tc + 2 * jt;       // actual output column (c0; c1=+1)
            float bx = 0.f, by = 0.f;
            if (isU) { bx = b1s[c0]; by = b1s[c0 + 1]; }
            h0[jt] = f2h2(acc[jt][0] + bx, acc[jt][1] + by);
            h1[jt] = f2h2(acc[jt][2] + bx, acc[jt][3] + by);
        }
        uint4* p0 = (uint4*)(table + (size_t)(nb + g) * HID + tc * 16);
        uint4* p1 = (uint4*)(table + (size_t)(nb + g + 8) * HID + tc * 16);
        p0[0] = make_uint4(h0[0], h0[1], h0[2], h0[3]);
        p0[1] = make_uint4(h0[4], h0[5], h0[6], h0[7]);
        p1[0] = make_uint4(h1[0], h1[1], h1[2], h1[3]);
        p1[1] = make_uint4(h1[4], h1[5], h1[6], h1[7]);
    }
}

// ---------------------------------------------------------------------------
// Phase 2: per-edge decode on fp16 tables — at the ~12 TB/s LTS roofline.
// Single resident wave (1184 CTAs), 8 lanes/edge, two edge slots per trip,
// half2 math, fp32 shuffle reduce. launch_bounds(256,8) pins 32 regs.
// ---------------------------------------------------------------------------
__global__ void __launch_bounds__(256, 8) edge_kernel(
    const int* __restrict__ idx,         // [2][E] int32
    const float* __restrict__ W2,        // [1][64]
    const float* __restrict__ b2,        // [1]
    float* __restrict__ out,             // [E]
    int E)
{
    int lane = threadIdx.x & 31;
    int q  = lane >> 3;                  // edge slot within warp-pass (0..3)
    int l8 = lane & 7;                   // feature chunk: 8 halves per lane

    float4 w0 = ((const float4*)W2)[2 * l8];
    float4 w1 = ((const float4*)W2)[2 * l8 + 1];
    __half2 wh0 = __floats2half2_rn(w0.x, w0.y);
    __half2 wh1 = __floats2half2_rn(w0.z, w0.w);
    __half2 wh2 = __floats2half2_rn(w1.x, w1.y);
    __half2 wh3 = __floats2half2_rn(w1.z, w1.w);
    float  b2v = b2[0];

    int gw = (blockIdx.x * blockDim.x + threadIdx.x) >> 5;
    int warps = (gridDim.x * blockDim.x) >> 5;

    const __half2 zero2 = __float2half2_rn(0.f);

    for (int e0 = gw * 8; e0 < E; e0 += warps * 8) {
        int eA = e0 + q;
        int eB = e0 + 4 + q;
        bool vA = (eA < E);
        bool vB = (eB < E);

        int rA = vA ? idx[eA]     : 0;
        int cA = vA ? idx[E + eA] : 0;
        int rB = vB ? idx[eB]     : 0;
        int cB = vB ? idx[E + eB] : 0;

        // 4 independent 16B gathers per thread
        uint4 uA = *(const uint4*)(g_U + (size_t)rA * HID + l8 * 8);
        uint4 bA = *(const uint4*)(g_B + (size_t)cA * HID + l8 * 8);
        uint4 uB = *(const uint4*)(g_U + (size_t)rB * HID + l8 * 8);
        uint4 bB = *(const uint4*)(g_B + (size_t)cB * HID + l8 * 8);

        float pA, pB;
        {
            const __half2* u = (const __half2*)&uA;
            const __half2* b = (const __half2*)&bA;
            __half2 h0 = __hmax2(__hadd2(u[0], b[0]), zero2);
            __half2 h1 = __hmax2(__hadd2(u[1], b[1]), zero2);
            __half2 h2 = __hmax2(__hadd2(u[2], b[2]), zero2);
            __half2 h3 = __hmax2(__hadd2(u[3], b[3]), zero2);
            __half2 a = __hmul2(h0, wh0);
            a = __hfma2(h1, wh1, a);
            a = __hfma2(h2, wh2, a);
            a = __hfma2(h3, wh3, a);
            float2 f = __half22float2(a);
            pA = f.x + f.y;
        }
        {
            const __half2* u = (const __half2*)&uB;
            const __half2* b = (const __half2*)&bB;
            __half2 h0 = __hmax2(__hadd2(u[0], b[0]), zero2);
            __half2 h1 = __hmax2(__hadd2(u[1], b[1]), zero2);
            __half2 h2 = __hmax2(__hadd2(u[2], b[2]), zero2);
            __half2 h3 = __hmax2(__hadd2(u[3], b[3]), zero2);
            __half2 a = __hmul2(h0, wh0);
            a = __hfma2(h1, wh1, a);
            a = __hfma2(h2, wh2, a);
            a = __hfma2(h3, wh3, a);
            float2 f = __half22float2(a);
            pB = f.x + f.y;
        }

        pA += __shfl_xor_sync(0xffffffffu, pA, 1);
        pB += __shfl_xor_sync(0xffffffffu, pB, 1);
        pA += __shfl_xor_sync(0xffffffffu, pA, 2);
        pB += __shfl_xor_sync(0xffffffffu, pB, 2);
        pA += __shfl_xor_sync(0xffffffffu, pA, 4);
        pB += __shfl_xor_sync(0xffffffffu, pB, 4);

        if (l8 == 0) {
            if (vA) out[eA] = pA + b2v;
            if (vB) out[eB] = pB + b2v;
        }
    }
}

// ---------------------------------------------------------------------------
extern "C" void kernel_launch(void* const* d_in, const int* in_sizes, int n_in,
                              void* d_out, int out_size)
{
    const float* z_user  = (const float*)d_in[0];
    const float* z_books = (const float*)d_in[1];
    const int*   idx     = (const int*)d_in[2];
    const float* W1      = (const float*)d_in[3];
    const float* b1      = (const float*)d_in[4];
    const float* W2      = (const float*)d_in[5];
    const float* b2      = (const float*)d_in[6];
    float*       out     = (float*)d_out;

    int E = in_sizes[2] / 2;             // edge_label_index is [2, E]

    // Phase 1: grid-stride, 2 warp-tiles per warp
    precompute_mma<<<PRE_BLOCKS, 256>>>(z_user, z_books, W1, b1);

    // Phase 2: single resident wave, 9472 warps * 8 edges per trip
    edge_kernel<<<EDGE_BLOCKS, 256>>>(idx, W2, b2, out, E);
}

// round 14
// speedup vs baseline: 3.1106x; 1.0341x over previous
#include <cuda_runtime.h>
#include <cuda_fp16.h>
#include <cstdint>

#define NUM_NODES 100000
#define HID 64
#define WTILES_PER_HALF (NUM_NODES / 16)      // 6250 warp-tiles per table
#define WTILES_TOTAL (2 * WTILES_PER_HALF)    // 12500
#define PRE_BLOCKS 592                        // 148 SMs x 4 resident: 1 wave
#define EDGE_BLOCKS 1184                      // 148 SMs x 8 CTAs: single wave

// Scratch tables in fp16 (allocation-free rule: __device__ globals).
__device__ __half g_U[NUM_NODES * HID];
__device__ __half g_B[NUM_NODES * HID];

__device__ __forceinline__ uint32_t f2h2(float x, float y) {
    __half2 h = __floats2half2_rn(x, y);
    return *reinterpret_cast<uint32_t*>(&h);
}
__device__ __forceinline__ void mma_f16(float* c, uint32_t a0, uint32_t a1,
                                        uint32_t a2, uint32_t a3,
                                        uint32_t b0, uint32_t b1) {
    asm volatile(
        "mma.sync.aligned.m16n8k16.row.col.f32.f16.f16.f32 "
        "{%0,%1,%2,%3}, {%4,%5,%6,%7}, {%8,%9}, {%0,%1,%2,%3};"
        : "+f"(c[0]), "+f"(c[1]), "+f"(c[2]), "+f"(c[3])
        : "r"(a0), "r"(a1), "r"(a2), "r"(a3), "r"(b0), "r"(b1));
}

// ---------------------------------------------------------------------------
// Phase 1: single-pass fp16 HMMA GEMM (fp32 accumulate, fp16 store).
// Output-column permutation: MMA jt covers actual cols {16q+2jt(+1), q=0..3},
// i.e. actual col j sits in MMA jt=(j&15)>>1 at fragment slot f=2*(j>>4)+(j&1).
// Lane tc then owns contiguous half2 cols 8tc..8tc+7 -> epilogue is
// 4 coalesced STG.128 per thread instead of 16 scattered STG.32.
// One warp-tile = 16 nodes x 64 outputs, K=64 -> 8 jt x 4 ks = 32 MMAs.
// Tiles [0,6250) -> U (+b1), rest -> B. Grid-stride: 2-3 tiles per warp,
// exactly one resident block-wave (592 CTAs at 4/SM).
// ---------------------------------------------------------------------------
__global__ void __launch_bounds__(256, 4) precompute_mma(
    const float* __restrict__ z_user,
    const float* __restrict__ z_books,
    const float* __restrict__ W1,    // [64][128]
    const float* __restrict__ b1)    // [64]
{
    __shared__ uint32_t Wq[4096];    // 16 KB fragment-layout W
    __shared__ float b1s[64];

    int tid = threadIdx.x;
    #pragma unroll
    for (int it = 0; it < 16; it++) {
        int i = it * 256 + tid;          // linear element 0..4095
        int half = i >> 11;              // 0 = user cols, 1 = book cols
        int j    = (i >> 5) & 63;
        int k2   = i & 31;
        float2 w = *(const float2*)(W1 + j * 128 + half * 64 + k2 * 2);
        int jt = (j & 15) >> 1;          // permuted MMA index
        int f  = 2 * (j >> 4) + (j & 1); // fragment n-slot
        int ks = k2 >> 3, t = k2 & 7, tc = t & 3, sel = t >> 2;
        int entry = (((half * 8 + jt) * 4 + ks) * 8 + f) * 4 + tc;
        Wq[entry * 2 + sel] = f2h2(w.x, w.y);
    }
    if (tid < 64) b1s[tid] = b1[tid];
    __syncthreads();

    int wid = tid >> 5, lane = tid & 31;
    int g = lane >> 2, tc = lane & 3;

    for (int wt = blockIdx.x * 8 + wid; wt < WTILES_TOTAL; wt += PRE_BLOCKS * 8) {
        bool isU = (wt < WTILES_PER_HALF);
        int tile = isU ? wt : wt - WTILES_PER_HALF;
        int nb = tile * 16;
        const float* z = isU ? z_user : z_books;
        int half = isU ? 0 : 1;

        const float2* zr0 = (const float2*)(z + (size_t)(nb + g) * HID);
        const float2* zr1 = (const float2*)(z + (size_t)(nb + g + 8) * HID);

        float acc[8][4];
        #pragma unroll
        for (int jt = 0; jt < 8; jt++)
            #pragma unroll
            for (int c = 0; c < 4; c++) acc[jt][c] = 0.f;

        #pragma unroll
        for (int ks = 0; ks < 4; ks++) {
            // A fragments: rows g / g+8, k pairs (ks*16+tc*2, +1), (+8, +9)
            float2 p00 = zr0[ks * 8 + tc],     p02 = zr0[ks * 8 + tc + 4];
            float2 p10 = zr1[ks * 8 + tc],     p12 = zr1[ks * 8 + tc + 4];
            uint32_t a0 = f2h2(p00.x, p00.y);
            uint32_t a1 = f2h2(p10.x, p10.y);
            uint32_t a2 = f2h2(p02.x, p02.y);
            uint32_t a3 = f2h2(p12.x, p12.y);

            #pragma unroll
            for (int jt = 0; jt < 8; jt++) {
                int entry = (((half * 8 + jt) * 4 + ks) * 8 + g) * 4 + tc;
                uint2 b = *(const uint2*)(Wq + entry * 2);  // conflict-free LDS.64
                mma_f16(acc[jt], a0, a1, a2, a3, b.x, b.y);
            }
        }

        // Epilogue: lane (g,tc) owns rows g/g+8, half2 cols 8tc+jt (jt=0..7).
        __half* table = isU ? g_U : g_B;
        uint32_t h0[8], h1[8];
        #pragma unroll
        for (int jt = 0; jt < 8; jt++) {
            int c0 = 16 * tc + 2 * jt;       // actual output column (c0; c1=+1)
            float bx = 0.f, by = 0.f;
            if (isU) { bx = b1s[c0]; by = b1s[c0 + 1]; }
            h0[jt] = f2h2(acc[jt][0] + bx, acc[jt][1] + by);
            h1[jt] = f2h2(acc[jt][2] + bx, acc[jt][3] + by);
        }
        uint4* p0 = (uint4*)(table + (size_t)(nb + g) * HID + tc * 16);
        uint4* p1 = (uint4*)(table + (size_t)(nb + g + 8) * HID + tc * 16);
        p0[0] = make_uint4(h0[0], h0[1], h0[2], h0[3]);
        p0[1] = make_uint4(h0[4], h0[5], h0[6], h0[7]);
        p1[0] = make_uint4(h1[0], h1[1], h1[2], h1[3]);
        p1[1] = make_uint4(h1[4], h1[5], h1[6], h1[7]);
    }
}

// ---------------------------------------------------------------------------
// Phase 2: per-edge decode on fp16 tables — at the ~13 TB/s LTS roofline.
// Single resident wave (1184 CTAs), 8 lanes/edge, two edge slots per trip,
// half2 math, fp32 shuffle reduce. launch_bounds(256,8) pins 32 regs.
// ---------------------------------------------------------------------------
__global__ void __launch_bounds__(256, 8) edge_kernel(
    const int* __restrict__ idx,         // [2][E] int32
    const float* __restrict__ W2,        // [1][64]
    const float* __restrict__ b2,        // [1]
    float* __restrict__ out,             // [E]
    int E)
{
    int lane = threadIdx.x & 31;
    int q  = lane >> 3;                  // edge slot within warp-pass (0..3)
    int l8 = lane & 7;                   // feature chunk: 8 halves per lane

    float4 w0 = ((const float4*)W2)[2 * l8];
    float4 w1 = ((const float4*)W2)[2 * l8 + 1];
    __half2 wh0 = __floats2half2_rn(w0.x, w0.y);
    __half2 wh1 = __floats2half2_rn(w0.z, w0.w);
    __half2 wh2 = __floats2half2_rn(w1.x, w1.y);
    __half2 wh3 = __floats2half2_rn(w1.z, w1.w);
    float  b2v = b2[0];

    int gw = (blockIdx.x * blockDim.x + threadIdx.x) >> 5;
    int warps = (gridDim.x * blockDim.x) >> 5;

    const __half2 zero2 = __float2half2_rn(0.f);

    for (int e0 = gw * 8; e0 < E; e0 += warps * 8) {
        int eA = e0 + q;
        int eB = e0 + 4 + q;
        bool vA = (eA < E);
        bool vB = (eB < E);

        int rA = vA ? idx[eA]     : 0;
        int cA = vA ? idx[E + eA] : 0;
        int rB = vB ? idx[eB]     : 0;
        int cB = vB ? idx[E + eB] : 0;

        // 4 independent 16B gathers per thread
        uint4 uA = *(const uint4*)(g_U + (size_t)rA * HID + l8 * 8);
        uint4 bA = *(const uint4*)(g_B + (size_t)cA * HID + l8 * 8);
        uint4 uB = *(const uint4*)(g_U + (size_t)rB * HID + l8 * 8);
        uint4 bB = *(const uint4*)(g_B + (size_t)cB * HID + l8 * 8);

        float pA, pB;
        {
            const __half2* u = (const __half2*)&uA;
            const __half2* b = (const __half2*)&bA;
            __half2 h0 = __hmax2(__hadd2(u[0], b[0]), zero2);
            __half2 h1 = __hmax2(__hadd2(u[1], b[1]), zero2);
            __half2 h2 = __hmax2(__hadd2(u[2], b[2]), zero2);
            __half2 h3 = __hmax2(__hadd2(u[3], b[3]), zero2);
            __half2 a = __hmul2(h0, wh0);
            a = __hfma2(h1, wh1, a);
            a = __hfma2(h2, wh2, a);
            a = __hfma2(h3, wh3, a);
            float2 f = __half22float2(a);
            pA = f.x + f.y;
        }
        {
            const __half2* u = (const __half2*)&uB;
            const __half2* b = (const __half2*)&bB;
            __half2 h0 = __hmax2(__hadd2(u[0], b[0]), zero2);
            __half2 h1 = __hmax2(__hadd2(u[1], b[1]), zero2);
            __half2 h2 = __hmax2(__hadd2(u[2], b[2]), zero2);
            __half2 h3 = __hmax2(__hadd2(u[3], b[3]), zero2);
            __half2 a = __hmul2(h0, wh0);
            a = __hfma2(h1, wh1, a);
            a = __hfma2(h2, wh2, a);
            a = __hfma2(h3, wh3, a);
            float2 f = __half22float2(a);
            pB = f.x + f.y;
        }

        pA += __shfl_xor_sync(0xffffffffu, pA, 1);
        pB += __shfl_xor_sync(0xffffffffu, pB, 1);
        pA += __shfl_xor_sync(0xffffffffu, pA, 2);
        pB += __shfl_xor_sync(0xffffffffu, pB, 2);
        pA += __shfl_xor_sync(0xffffffffu, pA, 4);
        pB += __shfl_xor_sync(0xffffffffu, pB, 4);

        if (l8 == 0) {
            if (vA) out[eA] = pA + b2v;
            if (vB) out[eB] = pB + b2v;
        }
    }
}

// ---------------------------------------------------------------------------
extern "C" void kernel_launch(void* const* d_in, const int* in_sizes, int n_in,
                              void* d_out, int out_size)
{
    const float* z_user  = (const float*)d_in[0];
    const float* z_books = (const float*)d_in[1];
    const int*   idx     = (const int*)d_in[2];
    const float* W1      = (const float*)d_in[3];
    const float* b1      = (const float*)d_in[4];
    const float* W2      = (const float*)d_in[5];
    const float* b2      = (const float*)d_in[6];
    float*       out     = (float*)d_out;

    int E = in_sizes[2] / 2;             // edge_label_index is [2, E]

    // Phase 1: single resident wave, grid-stride 2-3 warp-tiles per warp
    precompute_mma<<<PRE_BLOCKS, 256>>>(z_user, z_books, W1, b1);

    // Phase 2: single resident wave, 9472 warps * 8 edges per trip
    edge_kernel<<<EDGE_BLOCKS, 256>>>(idx, W2, b2, out, E);
}

// round 15
// speedup vs baseline: 3.2425x; 1.0424x over previous
#include <cuda_runtime.h>
#include <cuda_fp16.h>
#include <cstdint>

#define NUM_NODES 100000
#define HID 64
#define WTILES_PER_HALF (NUM_NODES / 16)      // 6250 warp-tiles per table
#define WTILES_TOTAL (2 * WTILES_PER_HALF)    // 12500
#define PRE_BLOCKS 592                        // 148 SMs x 4 resident: 1 wave
#define EDGE_BLOCKS 1184                      // 148 SMs x 8 CTAs: single wave

// Scratch tables in fp16 (allocation-free rule: __device__ globals).
__device__ __half g_U[NUM_NODES * HID];
__device__ __half g_B[NUM_NODES * HID];

__device__ __forceinline__ uint32_t f2h2(float x, float y) {
    __half2 h = __floats2half2_rn(x, y);
    return *reinterpret_cast<uint32_t*>(&h);
}
__device__ __forceinline__ void mma_f16(float* c, uint32_t a0, uint32_t a1,
                                        uint32_t a2, uint32_t a3,
                                        uint32_t b0, uint32_t b1) {
    asm volatile(
        "mma.sync.aligned.m16n8k16.row.col.f32.f16.f16.f32 "
        "{%0,%1,%2,%3}, {%4,%5,%6,%7}, {%8,%9}, {%0,%1,%2,%3};"
        : "+f"(c[0]), "+f"(c[1]), "+f"(c[2]), "+f"(c[3])
        : "r"(a0), "r"(a1), "r"(a2), "r"(a3), "r"(b0), "r"(b1));
}

// ---------------------------------------------------------------------------
// Phase 1: single-pass fp16 HMMA GEMM (fp32 accumulate, fp16 store).
//
// Output-column permutation (unchanged from R12): actual col j sits in MMA
// jt=(j&15)>>1 at fragment slot f=2*(j>>4)+(j&1) -> lane tc owns contiguous
// half2 cols 8tc..8tc+7 -> 4 coalesced STG.128 epilogue.
//
// K-axis permutation (new): lane tc's A fragments per K16-step are the
// contiguous physical k-pairs (8ks+2tc, 8ks+2tc+1) -> ONE float4 load per
// row per step (lanes tc=0..3 cover 64 B contiguously) instead of two
// strided float2 loads. Wq stores W at the same physical pairs, so the
// product is invariant.
//
// One warp-tile = 16 nodes x 64 outputs, K=64 -> 8 jt x 4 ks = 32 MMAs.
// Tiles [0,6250) -> U (+b1), rest -> B. Single resident block-wave.
// ---------------------------------------------------------------------------
__global__ void __launch_bounds__(256, 4) precompute_mma(
    const float* __restrict__ z_user,
    const float* __restrict__ z_books,
    const float* __restrict__ W1,    // [64][128]
    const float* __restrict__ b1)    // [64]
{
    __shared__ uint32_t Wq[4096];    // 16 KB fragment-layout W
    __shared__ float b1s[64];

    int tid = threadIdx.x;
    #pragma unroll
    for (int it = 0; it < 16; it++) {
        int i = it * 256 + tid;          // linear element 0..4095
        int half = i >> 11;              // 0 = user cols, 1 = book cols
        int j    = (i >> 5) & 63;
        int k2   = i & 31;               // physical k-pair index
        float2 w = *(const float2*)(W1 + j * 128 + half * 64 + k2 * 2);
        int jt = (j & 15) >> 1;          // permuted MMA index
        int f  = 2 * (j >> 4) + (j & 1); // fragment n-slot
        int ks = k2 >> 3, t = k2 & 7;
        int tc = t >> 1, sel = t & 1;    // K-permuted: pair (8ks+2tc+sel)
        int entry = (((half * 8 + jt) * 4 + ks) * 8 + f) * 4 + tc;
        Wq[entry * 2 + sel] = f2h2(w.x, w.y);
    }
    if (tid < 64) b1s[tid] = b1[tid];
    __syncthreads();

    int wid = tid >> 5, lane = tid & 31;
    int g = lane >> 2, tc = lane & 3;

    for (int wt = blockIdx.x * 8 + wid; wt < WTILES_TOTAL; wt += PRE_BLOCKS * 8) {
        bool isU = (wt < WTILES_PER_HALF);
        int tile = isU ? wt : wt - WTILES_PER_HALF;
        int nb = tile * 16;
        const float* z = isU ? z_user : z_books;
        int half = isU ? 0 : 1;

        const float4* zr0 = (const float4*)(z + (size_t)(nb + g) * HID);
        const float4* zr1 = (const float4*)(z + (size_t)(nb + g + 8) * HID);

        float acc[8][4];
        #pragma unroll
        for (int jt = 0; jt < 8; jt++)
            #pragma unroll
            for (int c = 0; c < 4; c++) acc[jt][c] = 0.f;

        #pragma unroll
        for (int ks = 0; ks < 4; ks++) {
            // A fragments: one float4 per row covers both k-pairs for lane tc
            float4 q0 = zr0[ks * 4 + tc];
            float4 q1 = zr1[ks * 4 + tc];
            uint32_t a0 = f2h2(q0.x, q0.y);   // pair 8ks+2tc   , row g
            uint32_t a2 = f2h2(q0.z, q0.w);   // pair 8ks+2tc+1 , row g
            uint32_t a1 = f2h2(q1.x, q1.y);   // pair 8ks+2tc   , row g+8
            uint32_t a3 = f2h2(q1.z, q1.w);   // pair 8ks+2tc+1 , row g+8

            #pragma unroll
            for (int jt = 0; jt < 8; jt++) {
                int entry = (((half * 8 + jt) * 4 + ks) * 8 + g) * 4 + tc;
                uint2 b = *(const uint2*)(Wq + entry * 2);  // conflict-free LDS.64
                mma_f16(acc[jt], a0, a1, a2, a3, b.x, b.y);
            }
        }

        // Epilogue: lane (g,tc) owns rows g/g+8, half2 cols 8tc+jt (jt=0..7).
        __half* table = isU ? g_U : g_B;
        uint32_t h0[8], h1[8];
        #pragma unroll
        for (int jt = 0; jt < 8; jt++) {
            int c0 = 16 * tc + 2 * jt;       // actual output column (c0; c1=+1)
            float bx = 0.f, by = 0.f;
            if (isU) { bx = b1s[c0]; by = b1s[c0 + 1]; }
            h0[jt] = f2h2(acc[jt][0] + bx, acc[jt][1] + by);
            h1[jt] = f2h2(acc[jt][2] + bx, acc[jt][3] + by);
        }
        uint4* p0 = (uint4*)(table + (size_t)(nb + g) * HID + tc * 16);
        uint4* p1 = (uint4*)(table + (size_t)(nb + g + 8) * HID + tc * 16);
        p0[0] = make_uint4(h0[0], h0[1], h0[2], h0[3]);
        p0[1] = make_uint4(h0[4], h0[5], h0[6], h0[7]);
        p1[0] = make_uint4(h1[0], h1[1], h1[2], h1[3]);
        p1[1] = make_uint4(h1[4], h1[5], h1[6], h1[7]);
    }
}

// ---------------------------------------------------------------------------
// Phase 2: per-edge decode on fp16 tables — at the ~13 TB/s LTS roofline.
// Single resident wave (1184 CTAs), 8 lanes/edge, two edge slots per trip,
// half2 math, fp32 shuffle reduce. launch_bounds(256,8) pins 32 regs.
// ---------------------------------------------------------------------------
__global__ void __launch_bounds__(256, 8) edge_kernel(
    const int* __restrict__ idx,         // [2][E] int32
    const float* __restrict__ W2,        // [1][64]
    const float* __restrict__ b2,        // [1]
    float* __restrict__ out,             // [E]
    int E)
{
    int lane = threadIdx.x & 31;
    int q  = lane >> 3;                  // edge slot within warp-pass (0..3)
    int l8 = lane & 7;                   // feature chunk: 8 halves per lane

    float4 w0 = ((const float4*)W2)[2 * l8];
    float4 w1 = ((const float4*)W2)[2 * l8 + 1];
    __half2 wh0 = __floats2half2_rn(w0.x, w0.y);
    __half2 wh1 = __floats2half2_rn(w0.z, w0.w);
    __half2 wh2 = __floats2half2_rn(w1.x, w1.y);
    __half2 wh3 = __floats2half2_rn(w1.z, w1.w);
    float  b2v = b2[0];

    int gw = (blockIdx.x * blockDim.x + threadIdx.x) >> 5;
    int warps = (gridDim.x * blockDim.x) >> 5;

    const __half2 zero2 = __float2half2_rn(0.f);

    for (int e0 = gw * 8; e0 < E; e0 += warps * 8) {
        int eA = e0 + q;
        int eB = e0 + 4 + q;
        bool vA = (eA < E);
        bool vB = (eB < E);

        int rA = vA ? idx[eA]     : 0;
        int cA = vA ? idx[E + eA] : 0;
        int rB = vB ? idx[eB]     : 0;
        int cB = vB ? idx[E + eB] : 0;

        // 4 independent 16B gathers per thread
        uint4 uA = *(const uint4*)(g_U + (size_t)rA * HID + l8 * 8);
        uint4 bA = *(const uint4*)(g_B + (size_t)cA * HID + l8 * 8);
        uint4 uB = *(const uint4*)(g_U + (size_t)rB * HID + l8 * 8);
        uint4 bB = *(const uint4*)(g_B + (size_t)cB * HID + l8 * 8);

        float pA, pB;
        {
            const __half2* u = (const __half2*)&uA;
            const __half2* b = (const __half2*)&bA;
            __half2 h0 = __hmax2(__hadd2(u[0], b[0]), zero2);
            __half2 h1 = __hmax2(__hadd2(u[1], b[1]), zero2);
            __half2 h2 = __hmax2(__hadd2(u[2], b[2]), zero2);
            __half2 h3 = __hmax2(__hadd2(u[3], b[3]), zero2);
            __half2 a = __hmul2(h0, wh0);
            a = __hfma2(h1, wh1, a);
            a = __hfma2(h2, wh2, a);
            a = __hfma2(h3, wh3, a);
            float2 f = __half22float2(a);
            pA = f.x + f.y;
        }
        {
            const __half2* u = (const __half2*)&uB;
            const __half2* b = (const __half2*)&bB;
            __half2 h0 = __hmax2(__hadd2(u[0], b[0]), zero2);
            __half2 h1 = __hmax2(__hadd2(u[1], b[1]), zero2);
            __half2 h2 = __hmax2(__hadd2(u[2], b[2]), zero2);
            __half2 h3 = __hmax2(__hadd2(u[3], b[3]), zero2);
            __half2 a = __hmul2(h0, wh0);
            a = __hfma2(h1, wh1, a);
            a = __hfma2(h2, wh2, a);
            a = __hfma2(h3, wh3, a);
            float2 f = __half22float2(a);
            pB = f.x + f.y;
        }

        pA += __shfl_xor_sync(0xffffffffu, pA, 1);
        pB += __shfl_xor_sync(0xffffffffu, pB, 1);
        pA += __shfl_xor_sync(0xffffffffu, pA, 2);
        pB += __shfl_xor_sync(0xffffffffu, pB, 2);
        pA += __shfl_xor_sync(0xffffffffu, pA, 4);
        pB += __shfl_xor_sync(0xffffffffu, pB, 4);

        if (l8 == 0) {
            if (vA) out[eA] = pA + b2v;
            if (vB) out[eB] = pB + b2v;
        }
    }
}

// ---------------------------------------------------------------------------
extern "C" void kernel_launch(void* const* d_in, const int* in_sizes, int n_in,
                              void* d_out, int out_size)
{
    const float* z_user  = (const float*)d_in[0];
    const float* z_books = (const float*)d_in[1];
    const int*   idx     = (const int*)d_in[2];
    const float* W1      = (const float*)d_in[3];
    const float* b1      = (const float*)d_in[4];
    const float* W2      = (const float*)d_in[5];
    const float* b2      = (const float*)d_in[6];
    float*       out     = (float*)d_out;

    int E = in_sizes[2] / 2;             // edge_label_index is [2, E]

    // Phase 1: single resident wave, grid-stride 2-3 warp-tiles per warp
    precompute_mma<<<PRE_BLOCKS, 256>>>(z_user, z_books, W1, b1);

    // Phase 2: single resident wave, 9472 warps * 8 edges per trip
    edge_kernel<<<EDGE_BLOCKS, 256>>>(idx, W2, b2, out, E);
}